// round 4
// baseline (speedup 1.0000x reference)
#include <cuda_runtime.h>
#include <math.h>

#define BATCH 2
#define HWd   192
#define HW2   (HWd*HWd)      // 36864
#define HGd   48
#define Ntok  (HGd*HGd)      // 2304
#define D2    256
#define VDdim 2048
#define NFtot 3
#define SELCAP 64
#define NROWS (BATCH*NFtot*Ntok)   // 13824
#define VSROW 68                    // padded smem row (floats) for 64-dim chunk

// ---------------- scratch (device globals; no allocs allowed) ----------------
__device__ float g_buf1[(size_t)BATCH*384*HW2];   // 1x1 conv out: ch0..255 = qk, 256..383 = v
__device__ float g_buf2[(size_t)BATCH*384*HW2];   // after dw3x3
__device__ float g_buf3[(size_t)BATCH*512*HW2];   // ch0..255 = q2(1x1), 256..511 = k2(1x1)
__device__ float g_buf4[(size_t)BATCH*512*Ntok];  // after dw4x4 stride4  [b][ch][token]
__device__ float g_qtok[(size_t)BATCH*Ntok*D2];   // normalized q * temperature, token-major
__device__ float g_attn[(size_t)BATCH*NFtot*Ntok*Ntok];
__device__ float g_otok[(size_t)BATCH*NFtot*Ntok*VDdim];
__device__ int   g_selidx[(size_t)NROWS*SELCAP];
__device__ float g_selw  [(size_t)NROWS*SELCAP];
__device__ int   g_selcnt[NROWS];

// =============================================================================
// shared 128x128 fp32 GEMM tile body (8x8/thread, KTILE=16, K=128 fixed)
// =============================================================================
__device__ __forceinline__ void gemm128_body(
    const float* __restrict__ Atile,
    const float* __restrict__ Bbase,
    float (* __restrict__ As)[132], float (* __restrict__ Bs)[128],
    int t, float acc[8][8])
{
    int arow = t >> 1, akq = (t & 1) * 8;
    int bk = t >> 4, bn = (t & 15) * 4;
    const float* Ap = Atile + (long)arow * 128 + akq;
    int tx = t & 15, ty = t >> 4;
    #pragma unroll 1
    for (int k0 = 0; k0 < 128; k0 += 16) {
        float4 a0 = *(const float4*)(Ap + k0);
        float4 a1 = *(const float4*)(Ap + k0 + 4);
        const float* bsrc = Bbase + (long)(k0 + bk) * HW2;
        float4 b0 = *(const float4*)(bsrc + bn);
        float4 b1 = *(const float4*)(bsrc + bn + 64);
        __syncthreads();
        As[akq+0][arow]=a0.x; As[akq+1][arow]=a0.y; As[akq+2][arow]=a0.z; As[akq+3][arow]=a0.w;
        As[akq+4][arow]=a1.x; As[akq+5][arow]=a1.y; As[akq+6][arow]=a1.z; As[akq+7][arow]=a1.w;
        *(float4*)&Bs[bk][bn]    = b0;
        *(float4*)&Bs[bk][bn+64] = b1;
        __syncthreads();
        #pragma unroll
        for (int kk = 0; kk < 16; kk++) {
            float4 av0 = *(const float4*)&As[kk][ty*4];
            float4 av1 = *(const float4*)&As[kk][64+ty*4];
            float4 bv0 = *(const float4*)&Bs[kk][tx*4];
            float4 bv1 = *(const float4*)&Bs[kk][64+tx*4];
            float a8[8] = {av0.x,av0.y,av0.z,av0.w,av1.x,av1.y,av1.z,av1.w};
            float b8[8] = {bv0.x,bv0.y,bv0.z,bv0.w,bv1.x,bv1.y,bv1.z,bv1.w};
            #pragma unroll
            for (int i = 0; i < 8; i++)
                #pragma unroll
                for (int j = 0; j < 8; j++)
                    acc[i][j] += a8[i] * b8[j];
        }
    }
}

__device__ __forceinline__ void gemm128_store(
    float* __restrict__ Crow, const float* __restrict__ bias,
    int t, float acc[8][8], long ldc)
{
    int tx = t & 15, ty = t >> 4;
    #pragma unroll
    for (int i = 0; i < 8; i++) {
        int m = (i < 4) ? (ty*4 + i) : (64 + ty*4 + i - 4);
        float bv = bias[m];
        float4 o0 = {acc[i][0]+bv, acc[i][1]+bv, acc[i][2]+bv, acc[i][3]+bv};
        float4 o1 = {acc[i][4]+bv, acc[i][5]+bv, acc[i][6]+bv, acc[i][7]+bv};
        *(float4*)&Crow[(long)m*ldc + tx*4]      = o0;
        *(float4*)&Crow[(long)m*ldc + 64 + tx*4] = o1;
    }
}

// stage A: [qk(256ch) | v(128ch)] = W * x ; grid (288, 3, BATCH)
__global__ void __launch_bounds__(256) gemm_stageA(
    const float* __restrict__ x,
    const float* __restrict__ qk_w, const float* __restrict__ qk_b,
    const float* __restrict__ v_w,  const float* __restrict__ v_b)
{
    int n0 = blockIdx.x * 128, y = blockIdx.y, b = blockIdx.z;
    int t = threadIdx.x;
    __shared__ float As[16][132];
    __shared__ float Bs[16][128];
    float acc[8][8] = {};
    const float* A   = (y < 2) ? (qk_w + (long)y*128*128) : v_w;
    const float* bia = (y < 2) ? (qk_b + y*128)           : v_b;
    int cch          = (y < 2) ? (y*128)                  : 256;
    const float* Bbase = x + (long)b*128*HW2 + n0;
    gemm128_body(A, Bbase, As, Bs, t, acc);
    float* Crow = g_buf1 + ((long)b*384 + cch) * HW2 + n0;
    gemm128_store(Crow, bia, t, acc, HW2);
}

// stage C: q2 + k2 ; grid (288, 4, BATCH)
__global__ void __launch_bounds__(256) gemm_stageC(
    const float* __restrict__ q2_w, const float* __restrict__ q2_b,
    const float* __restrict__ k2_w, const float* __restrict__ k2_b)
{
    int n0 = blockIdx.x * 128, y = blockIdx.y, b = blockIdx.z;
    int t = threadIdx.x;
    __shared__ float As[16][132];
    __shared__ float Bs[16][128];
    float acc[8][8] = {};
    const float* A   = (y < 2) ? (q2_w + (long)y*128*128) : (k2_w + (long)(y-2)*128*128);
    const float* bia = (y < 2) ? (q2_b + y*128)           : (k2_b + (y-2)*128);
    const float* Bbase = g_buf2 + ((long)b*384 + ((y < 2) ? 0 : 128)) * HW2 + n0;
    gemm128_body(A, Bbase, As, Bs, t, acc);
    float* Crow = g_buf3 + ((long)b*512 + y*128) * HW2 + n0;
    gemm128_store(Crow, bia, t, acc, HW2);
}

// =============================================================================
// Attention GEMM: attn[query, key] = Q[query,:] . K[key,:]  (temp folded into Q)
// =============================================================================
__global__ void __launch_bounds__(256) attn_gemm2(
    const float* __restrict__ kc, const float* __restrict__ knew)
{
    int z = blockIdx.z; int b = z / NFtot, f = z % NFtot;
    const float* Qp = g_qtok + (long)b * Ntok * D2;
    const float* Kp = (f < 2) ? (kc   + ((long)(b*2 + f)) * Ntok * D2)
                              : (knew + ((long)(b*2 + 1)) * Ntok * D2);
    int m0 = blockIdx.y * 128;
    int n0 = blockIdx.x * 128;
    int t = threadIdx.x;
    int tx = t & 15, ty = t >> 4;
    __shared__ float As[16][132];
    __shared__ float Bs[16][132];
    float acc[8][8] = {};
    int row = t >> 1, kq = (t & 1) * 8;
    const float* Ap = Qp + (long)(m0 + row) * D2 + kq;
    const float* Bp = Kp + (long)(n0 + row) * D2 + kq;

    for (int k0 = 0; k0 < D2; k0 += 16) {
        float4 a0 = *(const float4*)(Ap + k0);
        float4 a1 = *(const float4*)(Ap + k0 + 4);
        float4 b0 = *(const float4*)(Bp + k0);
        float4 b1 = *(const float4*)(Bp + k0 + 4);
        __syncthreads();
        As[kq+0][row]=a0.x; As[kq+1][row]=a0.y; As[kq+2][row]=a0.z; As[kq+3][row]=a0.w;
        As[kq+4][row]=a1.x; As[kq+5][row]=a1.y; As[kq+6][row]=a1.z; As[kq+7][row]=a1.w;
        Bs[kq+0][row]=b0.x; Bs[kq+1][row]=b0.y; Bs[kq+2][row]=b0.z; Bs[kq+3][row]=b0.w;
        Bs[kq+4][row]=b1.x; Bs[kq+5][row]=b1.y; Bs[kq+6][row]=b1.z; Bs[kq+7][row]=b1.w;
        __syncthreads();
        #pragma unroll
        for (int kk = 0; kk < 16; kk++) {
            float4 av0 = *(const float4*)&As[kk][ty*4];
            float4 av1 = *(const float4*)&As[kk][64+ty*4];
            float4 bv0 = *(const float4*)&Bs[kk][tx*4];
            float4 bv1 = *(const float4*)&Bs[kk][64+tx*4];
            float a8[8] = {av0.x,av0.y,av0.z,av0.w,av1.x,av1.y,av1.z,av1.w};
            float b8[8] = {bv0.x,bv0.y,bv0.z,bv0.w,bv1.x,bv1.y,bv1.z,bv1.w};
            #pragma unroll
            for (int i = 0; i < 8; i++)
                #pragma unroll
                for (int j = 0; j < 8; j++)
                    acc[i][j] += a8[i] * b8[j];
        }
    }
    float* Cp = g_attn + (long)z * Ntok * Ntok;
    #pragma unroll
    for (int i = 0; i < 8; i++) {
        int m = (i < 4) ? (ty*4 + i) : (64 + ty*4 + i - 4);
        float4 o0 = {acc[i][0], acc[i][1], acc[i][2], acc[i][3]};
        float4 o1 = {acc[i][4], acc[i][5], acc[i][6], acc[i][7]};
        *(float4*)&Cp[(long)(m0+m)*Ntok + n0 + tx*4]      = o0;
        *(float4*)&Cp[(long)(m0+m)*Ntok + n0 + 64 + tx*4] = o1;
    }
}

// =============================================================================
// proj 1x1 GEMM with fused window de-permute gather
// =============================================================================
__global__ void __launch_bounds__(256) proj_gemm2(
    const float* __restrict__ W, const float* __restrict__ bias,
    float* __restrict__ Out)
{
    int z  = blockIdx.z;
    int n0 = blockIdx.x * 128;
    int t = threadIdx.x;
    int tx = t & 15, ty = t >> 4;
    __shared__ float As[16][132];
    __shared__ float Bs[16][132];
    float acc[8][8] = {};
    int row = t >> 1, kq = (t & 1) * 8;
    const float* Ap = W + (long)row * 128 + kq;
    int p = n0 + row;
    int h = p / HWd, w = p % HWd;
    int token = (h % HGd) * HGd + (w % HGd);
    int vbase = ((h / HGd) * 4 + (w / HGd)) * 128;
    const float* Bp = g_otok + ((long)z * Ntok + token) * VDdim + vbase + kq;

    for (int k0 = 0; k0 < 128; k0 += 16) {
        float4 a0 = *(const float4*)(Ap + k0);
        float4 a1 = *(const float4*)(Ap + k0 + 4);
        float4 b0 = *(const float4*)(Bp + k0);
        float4 b1 = *(const float4*)(Bp + k0 + 4);
        __syncthreads();
        As[kq+0][row]=a0.x; As[kq+1][row]=a0.y; As[kq+2][row]=a0.z; As[kq+3][row]=a0.w;
        As[kq+4][row]=a1.x; As[kq+5][row]=a1.y; As[kq+6][row]=a1.z; As[kq+7][row]=a1.w;
        Bs[kq+0][row]=b0.x; Bs[kq+1][row]=b0.y; Bs[kq+2][row]=b0.z; Bs[kq+3][row]=b0.w;
        Bs[kq+4][row]=b1.x; Bs[kq+5][row]=b1.y; Bs[kq+6][row]=b1.z; Bs[kq+7][row]=b1.w;
        __syncthreads();
        #pragma unroll
        for (int kk = 0; kk < 16; kk++) {
            float4 av0 = *(const float4*)&As[kk][ty*4];
            float4 av1 = *(const float4*)&As[kk][64+ty*4];
            float4 bv0 = *(const float4*)&Bs[kk][tx*4];
            float4 bv1 = *(const float4*)&Bs[kk][64+tx*4];
            float a8[8] = {av0.x,av0.y,av0.z,av0.w,av1.x,av1.y,av1.z,av1.w};
            float b8[8] = {bv0.x,bv0.y,bv0.z,bv0.w,bv1.x,bv1.y,bv1.z,bv1.w};
            #pragma unroll
            for (int i = 0; i < 8; i++)
                #pragma unroll
                for (int j = 0; j < 8; j++)
                    acc[i][j] += a8[i] * b8[j];
        }
    }
    #pragma unroll
    for (int i = 0; i < 8; i++) {
        int m = (i < 4) ? (ty*4 + i) : (64 + ty*4 + i - 4);
        float bv = bias[m];
        float4 o0 = {acc[i][0]+bv, acc[i][1]+bv, acc[i][2]+bv, acc[i][3]+bv};
        float4 o1 = {acc[i][4]+bv, acc[i][5]+bv, acc[i][6]+bv, acc[i][7]+bv};
        *(float4*)&Out[((long)z*128 + m)*HW2 + n0 + tx*4]      = o0;
        *(float4*)&Out[((long)z*128 + m)*HW2 + n0 + 64 + tx*4] = o1;
    }
}

// ---------------- depthwise 3x3 pad1 (on g_buf1 -> g_buf2) -------------------
__global__ void dw3x3(const float* __restrict__ qk_dw_w, const float* __restrict__ qk_dw_b,
                      const float* __restrict__ v_dw_w,  const float* __restrict__ v_dw_b)
{
    int idx = blockIdx.x * 256 + threadIdx.x;
    if (idx >= BATCH*384*HW2) return;
    int p  = idx % HW2;
    int ch = (idx / HW2) % 384;
    int b  = idx / (384*HW2);
    int h = p / HWd, w = p % HWd;
    const float* wgt; float bv;
    if (ch < 256) { wgt = qk_dw_w + ch*9;        bv = qk_dw_b[ch]; }
    else          { wgt = v_dw_w  + (ch-256)*9;  bv = v_dw_b[ch-256]; }
    const float* in = g_buf1 + ((long)(b*384 + ch)) * HW2;
    float s = bv;
    #pragma unroll
    for (int ky = 0; ky < 3; ky++) {
        int y = h + ky - 1;
        if ((unsigned)y >= (unsigned)HWd) continue;
        #pragma unroll
        for (int kx = 0; kx < 3; kx++) {
            int x = w + kx - 1;
            if ((unsigned)x >= (unsigned)HWd) continue;
            s += wgt[ky*3+kx] * in[y*HWd + x];
        }
    }
    g_buf2[idx] = s;
}

// ---------------- depthwise 4x4 stride4 pad1 (g_buf3 -> g_buf4) --------------
__global__ void dw4x4(const float* __restrict__ q2_dw_w, const float* __restrict__ q2_dw_b,
                      const float* __restrict__ k2_dw_w, const float* __restrict__ k2_dw_b)
{
    int idx = blockIdx.x * 256 + threadIdx.x;
    if (idx >= BATCH*512*Ntok) return;
    int t  = idx % Ntok;
    int ch = (idx / Ntok) % 512;
    int b  = idx / (512*Ntok);
    int oy = t / HGd, ox = t % HGd;
    const float* wgt; float bv;
    if (ch < 256) { wgt = q2_dw_w + ch*16;       bv = q2_dw_b[ch]; }
    else          { wgt = k2_dw_w + (ch-256)*16; bv = k2_dw_b[ch-256]; }
    const float* in = g_buf3 + ((long)(b*512 + ch)) * HW2;
    float s = bv;
    #pragma unroll
    for (int ky = 0; ky < 4; ky++) {
        int y = oy*4 - 1 + ky;
        if ((unsigned)y >= (unsigned)HWd) continue;
        #pragma unroll
        for (int kx = 0; kx < 4; kx++) {
            int x = ox*4 - 1 + kx;
            if ((unsigned)x >= (unsigned)HWd) continue;
            s += wgt[ky*4+kx] * in[y*HWd + x];
        }
    }
    g_buf4[idx] = s;
}

// ---------------- l2 normalize + token-major q/k (temp folded into q) --------
__global__ void __launch_bounds__(256) norm_qk(float* __restrict__ kout,
                                               const float* __restrict__ temp)
{
    int token = blockIdx.x, b = blockIdx.y, d = threadIdx.x;
    float qv = g_buf4[((long)b*512 + d)       * Ntok + token];
    float kv = g_buf4[((long)b*512 + 256 + d) * Ntok + token];
    __shared__ float red[256];
    __shared__ float qinv_s, kinv_s;
    red[d] = qv*qv; __syncthreads();
    for (int s = 128; s > 0; s >>= 1) { if (d < s) red[d] += red[d+s]; __syncthreads(); }
    if (d == 0) qinv_s = (*temp) / fmaxf(sqrtf(red[0]), 1e-12f);
    __syncthreads();
    red[d] = kv*kv; __syncthreads();
    for (int s = 128; s > 0; s >>= 1) { if (d < s) red[d] += red[d+s]; __syncthreads(); }
    if (d == 0) kinv_s = 1.f / fmaxf(sqrtf(red[0]), 1e-12f);
    __syncthreads();
    g_qtok[((long)b*Ntok + token) * D2 + d] = qv * qinv_s;
    kout  [((long)(b*2 + 1)*Ntok + token) * D2 + d] = kv * kinv_s;
}

// ---------------- build v_new (strided-window permute) into d_out ------------
__global__ void build_vnew(float* __restrict__ vout)
{
    int idx = blockIdx.x * 256 + threadIdx.x;
    if (idx >= BATCH*Ntok*VDdim) return;
    int vd    = idx % VDdim;
    int token = (idx / VDdim) % Ntok;
    int b     = idx / (Ntok*VDdim);
    int c  = vd & 127;
    int p2 = (vd >> 7) & 3;
    int p1 = vd >> 9;
    int hi = token / HGd, wi = token % HGd;
    float val = g_buf2[((long)(b*384 + 256 + c)) * HW2 + (p1*HGd + hi) * HWd + (p2*HGd + wi)];
    vout[((long)(b*2 + 1)*Ntok + token) * VDdim + vd] = val;
}

// =============================================================================
// sparse_select: top-k + local mask + softmax -> per-row (idx, weight) lists
// =============================================================================
__global__ void __launch_bounds__(256) sparse_select()
{
    int n = blockIdx.x, f = blockIdx.y, b = blockIdx.z;
    int rowid = (b*NFtot + f) * Ntok + n;
    const float* arow = g_attn + (long)rowid * Ntok;
    int tid = threadIdx.x;

    float t5[5] = {-INFINITY,-INFINITY,-INFINITY,-INFINITY,-INFINITY};
    for (int m = tid; m < Ntok; m += 256) {
        float v = arow[m];
        if (v > t5[4]) {
            t5[4] = v;
            #pragma unroll
            for (int i = 4; i > 0; i--)
                if (t5[i] > t5[i-1]) { float tmp = t5[i-1]; t5[i-1] = t5[i]; t5[i] = tmp; }
        }
    }
    __shared__ float cand[256*5];
    __shared__ float red[256];
    #pragma unroll
    for (int i = 0; i < 5; i++) cand[tid*5 + i] = t5[i];
    __syncthreads();

    float thr = INFINITY;
    for (int r = 0; r < 5; r++) {
        float lm = -INFINITY;
        #pragma unroll
        for (int i = 0; i < 5; i++) {
            float v = cand[tid*5 + i];
            if (v < thr && v > lm) lm = v;
        }
        red[tid] = lm; __syncthreads();
        for (int s = 128; s > 0; s >>= 1) { if (tid < s) red[tid] = fmaxf(red[tid], red[tid+s]); __syncthreads(); }
        thr = red[0];
        __syncthreads();
    }
    float kth = thr;

    __shared__ unsigned mask[72];
    __shared__ int base[73];
    if (tid < 72) mask[tid] = 0;
    __syncthreads();
    int ny = n / HGd, nx = n % HGd;
    for (int m = tid; m < Ntok; m += 256) {
        float a = arow[m];
        float coef = (a >= kth) ? 1.f : 0.f;
        int my = m / HGd, mx = m % HGd;
        if (abs(ny - my) + abs(nx - mx) <= 4) coef += 1.f;
        if (a * coef != 0.f) atomicOr(&mask[m >> 5], 1u << (m & 31));
    }
    __syncthreads();
    if (tid == 0) {
        int s = 0;
        for (int w = 0; w < 72; w++) { base[w] = s; s += __popc(mask[w]); }
        base[72] = s;
    }
    __syncthreads();
    int cnt = min(base[72], SELCAP);

    __shared__ int   sidx[SELCAP];
    __shared__ float sval[SELCAP];
    if (tid < 72) {
        unsigned bits = mask[tid];
        int pos = base[tid];
        while (bits) {
            int bit = __ffs(bits) - 1; bits &= bits - 1;
            if (pos < SELCAP) {
                int m = tid*32 + bit;
                float a = arow[m];
                float coef = (a >= kth) ? 1.f : 0.f;
                int my = m / HGd, mx = m % HGd;
                if (abs(ny - my) + abs(nx - mx) <= 4) coef += 1.f;
                sidx[pos] = m; sval[pos] = a * coef;
            }
            pos++;
        }
    }
    __syncthreads();

    __shared__ float smax, ssum;
    if (tid == 0) {
        float mx = -INFINITY;
        for (int e = 0; e < cnt; e++) mx = fmaxf(mx, sval[e]);
        smax = mx;
    }
    __syncthreads();
    if (tid < cnt) sval[tid] = expf(sval[tid] - smax);
    __syncthreads();
    if (tid == 0) {
        float s = 0.f;
        for (int e = 0; e < cnt; e++) s += sval[e];
        ssum = s;
    }
    __syncthreads();
    float inv = 1.f / ssum;
    if (tid < cnt) {
        g_selidx[(long)rowid*SELCAP + tid] = sidx[tid];
        g_selw  [(long)rowid*SELCAP + tid] = sval[tid] * inv;
    }
    if (tid == 0) g_selcnt[rowid] = cnt;
}

// =============================================================================
// sparse_av_tiled: 8x8 query subgrid per block, 64-dim chunk, smem-staged
// 16x16 token bounding box (covers every L1-diamond entry). Nonlocal topk
// entries (<=5/query) fall through to gmem.
// grid: (32 chunks, 36 tiles, 6 zf), block 256 = 64 queries x 4 lanes x 16 dims
// =============================================================================
__global__ void __launch_bounds__(256) sparse_av_tiled(
    const float* __restrict__ v_cached, const float* __restrict__ vout)
{
    extern __shared__ float vs[];            // [256 rows][VSROW]
    int chunk = blockIdx.x;                  // 0..31 (64 dims each)
    int tile  = blockIdx.y;                  // 0..35
    int z     = blockIdx.z;                  // b*3+f
    int b = z / NFtot, f = z % NFtot;
    const float* vbase = (f < 2) ? (v_cached + ((long)(b*2 + f)) * Ntok * VDdim)
                                 : (vout     + ((long)(b*2 + 1)) * Ntok * VDdim);
    int ty0 = (tile / 6) * 8, tx0 = (tile % 6) * 8;
    int by0 = ty0 - 4,        bx0 = tx0 - 4;
    int d0 = chunk * 64;
    int tid = threadIdx.x;

    // stage 16x16 token bbox x 64 dims into smem (zero-fill out-of-grid)
    for (int i = tid; i < 256 * 16; i += 256) {     // 16 float4 per row
        int r = i >> 4, c4 = i & 15;
        int gy = by0 + (r >> 4), gx = bx0 + (r & 15);
        float4 val = {0.f, 0.f, 0.f, 0.f};
        if ((unsigned)gy < (unsigned)HGd && (unsigned)gx < (unsigned)HGd)
            val = *(const float4*)&vbase[(long)(gy*HGd + gx) * VDdim + d0 + c4*4];
        *(float4*)&vs[r * VSROW + c4*4] = val;
    }
    __syncthreads();

    int q = tid >> 2, lane = tid & 3;        // 64 queries x 4 lanes
    int qy = ty0 + (q >> 3), qx = tx0 + (q & 7);
    int rowid = z * Ntok + qy * HGd + qx;
    int cnt = g_selcnt[rowid];
    const int*   sip = g_selidx + (long)rowid * SELCAP;
    const float* swp = g_selw   + (long)rowid * SELCAP;
    int dd = lane * 16;
    float acc[16] = {};

    for (int e = 0; e < cnt; e++) {
        int   m = sip[e];
        float w = swp[e];
        int my = m / HGd, mx = m % HGd;
        int ly = my - by0, lx = mx - bx0;
        const float* src;
        if ((unsigned)ly < 16u && (unsigned)lx < 16u)
            src = &vs[(ly*16 + lx) * VSROW + dd];
        else
            src = &vbase[(long)m * VDdim + d0 + dd];
        #pragma unroll
        for (int j = 0; j < 16; j += 4) {
            float4 v4 = *(const float4*)(src + j);
            acc[j+0] += w * v4.x; acc[j+1] += w * v4.y;
            acc[j+2] += w * v4.z; acc[j+3] += w * v4.w;
        }
    }
    float* orow = g_otok + (long)rowid * VDdim + d0 + dd;
    #pragma unroll
    for (int j = 0; j < 16; j += 4)
        *(float4*)(orow + j) = make_float4(acc[j], acc[j+1], acc[j+2], acc[j+3]);
}

// ---------------------------------- launch -----------------------------------
extern "C" void kernel_launch(void* const* d_in, const int* in_sizes, int n_in,
                              void* d_out, int out_size)
{
    (void)in_sizes; (void)n_in; (void)out_size;
    const float* x         = (const float*)d_in[0];
    const float* k_cached  = (const float*)d_in[1];
    const float* v_cached  = (const float*)d_in[2];
    const float* temperature = (const float*)d_in[3];
    const float* qk_w  = (const float*)d_in[4],  *qk_b  = (const float*)d_in[5];
    const float* qk_dw_w = (const float*)d_in[6], *qk_dw_b = (const float*)d_in[7];
    const float* v_w   = (const float*)d_in[8],  *v_b   = (const float*)d_in[9];
    const float* v_dw_w = (const float*)d_in[10], *v_dw_b = (const float*)d_in[11];
    const float* k2_w  = (const float*)d_in[12], *k2_b  = (const float*)d_in[13];
    const float* k2_dw_w = (const float*)d_in[14], *k2_dw_b = (const float*)d_in[15];
    const float* q2_w  = (const float*)d_in[16], *q2_b  = (const float*)d_in[17];
    const float* q2_dw_w = (const float*)d_in[18], *q2_dw_b = (const float*)d_in[19];
    const float* proj_w = (const float*)d_in[20], *proj_b = (const float*)d_in[21];

    float* out = (float*)d_out;
    const long OUT_K = (long)BATCH * NFtot * 128 * HW2;
    const long OUT_V = OUT_K + (long)BATCH * 2 * Ntok * D2;
    float* kout = out + OUT_K;
    float* vout = out + OUT_V;

    dim3 blk(256);
    const int AV_SMEM = 256 * VSROW * 4;     // 69632 B
    static int smem_set = 0;
    if (!smem_set) {
        cudaFuncSetAttribute(sparse_av_tiled,
                             cudaFuncAttributeMaxDynamicSharedMemorySize, AV_SMEM);
        smem_set = 1;
    }

    // stage A: fused 1x1 convs from x (qk 256ch + v 128ch)
    gemm_stageA<<<dim3(288,3,BATCH), blk>>>(x, qk_w, qk_b, v_w, v_b);
    // stage B: depthwise 3x3 pad1 on all 384 channels
    dw3x3<<<(BATCH*384*HW2 + 255)/256, blk>>>(qk_dw_w, qk_dw_b, v_dw_w, v_dw_b);
    // stage C: fused 1x1 convs q2 + k2
    gemm_stageC<<<dim3(288,4,BATCH), blk>>>(q2_w, q2_b, k2_w, k2_b);
    // stage D: depthwise 4x4 stride4 pad1 -> 48x48 token grid
    dw4x4<<<(BATCH*512*Ntok + 255)/256, blk>>>(q2_dw_w, q2_dw_b, k2_dw_w, k2_dw_b);
    // stage E: l2-normalize q/k (temperature folded into q); k_new into d_out
    norm_qk<<<dim3(Ntok, BATCH), blk>>>(kout, temperature);
    // stage F: v_new window permute straight into d_out
    build_vnew<<<(BATCH*Ntok*VDdim + 255)/256, blk>>>(vout);
    // cached slices -> output slots f'=0
    for (int b = 0; b < BATCH; b++) {
        cudaMemcpyAsync(kout + (long)(b*2)*Ntok*D2,
                        k_cached + (long)(b*2+1)*Ntok*D2,
                        (size_t)Ntok*D2*sizeof(float), cudaMemcpyDeviceToDevice, 0);
        cudaMemcpyAsync(vout + (long)(b*2)*Ntok*VDdim,
                        v_cached + (long)(b*2+1)*Ntok*VDdim,
                        (size_t)Ntok*VDdim*sizeof(float), cudaMemcpyDeviceToDevice, 0);
    }
    // stage G: attention logits (6 GEMMs via grid.z)
    attn_gemm2<<<dim3(18,18,BATCH*NFtot), blk>>>(k_cached, kout);
    // stage H1: top-k + local mask + softmax -> sparse lists
    sparse_select<<<dim3(Ntok, NFtot, BATCH), blk>>>();
    // stage H2: smem-deduped tiled sparse AV
    sparse_av_tiled<<<dim3(32, 36, BATCH*NFtot), blk, AV_SMEM>>>(v_cached, vout);
    // stage I: proj 1x1 with fused de-permute, writes final out
    proj_gemm2<<<dim3(288,1,BATCH*NFtot), blk>>>(proj_w, proj_b, out);
}

// round 6
// speedup vs baseline: 1.1799x; 1.1799x over previous
#include <cuda_runtime.h>
#include <math.h>

#define BATCH 2
#define HWd   192
#define HW2   (HWd*HWd)      // 36864
#define HGd   48
#define Ntok  (HGd*HGd)      // 2304
#define D2    256
#define VDdim 2048
#define NFtot 3
#define LISTCAP 128

// ---------------- scratch (device globals; no allocs allowed) ----------------
__device__ float g_buf1[(size_t)BATCH*384*HW2];
__device__ float g_buf2[(size_t)BATCH*384*HW2];
__device__ float g_buf3[(size_t)BATCH*512*HW2];
__device__ float g_buf4[(size_t)BATCH*512*Ntok];
__device__ float g_qtok[(size_t)BATCH*Ntok*D2];
__device__ float g_attn[(size_t)BATCH*NFtot*Ntok*Ntok];
__device__ float g_otok[(size_t)BATCH*NFtot*Ntok*VDdim];

// =============================================================================
// double-buffered conv GEMM body: A[128 x K] (row stride K), B (rows stride HW2)
// =============================================================================
__device__ __forceinline__ void gemm_db_conv(
    const float* __restrict__ A, const float* __restrict__ Bbase, int K,
    float (* __restrict__ As)[16][132], float (* __restrict__ Bs)[16][128],
    int t, float acc[8][8])
{
    int arow = t >> 1, akq = (t & 1) * 8;
    int bk = t >> 4, bn = (t & 15) * 4;
    int tx = t & 15, ty = t >> 4;
    const float* Ap = A + (long)arow * K + akq;

    float4 a0 = *(const float4*)(Ap);
    float4 a1 = *(const float4*)(Ap + 4);
    const float* bs0 = Bbase + (long)bk * HW2;
    float4 b0 = *(const float4*)(bs0 + bn);
    float4 b1 = *(const float4*)(bs0 + bn + 64);
    As[0][akq+0][arow]=a0.x; As[0][akq+1][arow]=a0.y; As[0][akq+2][arow]=a0.z; As[0][akq+3][arow]=a0.w;
    As[0][akq+4][arow]=a1.x; As[0][akq+5][arow]=a1.y; As[0][akq+6][arow]=a1.z; As[0][akq+7][arow]=a1.w;
    *(float4*)&Bs[0][bk][bn]    = b0;
    *(float4*)&Bs[0][bk][bn+64] = b1;
    __syncthreads();
    int buf = 0;
    for (int k0 = 16; k0 <= K; k0 += 16) {
        if (k0 < K) {
            a0 = *(const float4*)(Ap + k0);
            a1 = *(const float4*)(Ap + k0 + 4);
            const float* bs2 = Bbase + (long)(k0 + bk) * HW2;
            b0 = *(const float4*)(bs2 + bn);
            b1 = *(const float4*)(bs2 + bn + 64);
        }
        #pragma unroll
        for (int kk = 0; kk < 16; kk++) {
            float4 av0 = *(const float4*)&As[buf][kk][ty*4];
            float4 av1 = *(const float4*)&As[buf][kk][64+ty*4];
            float4 bv0 = *(const float4*)&Bs[buf][kk][tx*4];
            float4 bv1 = *(const float4*)&Bs[buf][kk][64+tx*4];
            float a8[8] = {av0.x,av0.y,av0.z,av0.w,av1.x,av1.y,av1.z,av1.w};
            float b8[8] = {bv0.x,bv0.y,bv0.z,bv0.w,bv1.x,bv1.y,bv1.z,bv1.w};
            #pragma unroll
            for (int i = 0; i < 8; i++)
                #pragma unroll
                for (int j = 0; j < 8; j++)
                    acc[i][j] += a8[i] * b8[j];
        }
        if (k0 < K) {
            int nb = buf ^ 1;
            As[nb][akq+0][arow]=a0.x; As[nb][akq+1][arow]=a0.y; As[nb][akq+2][arow]=a0.z; As[nb][akq+3][arow]=a0.w;
            As[nb][akq+4][arow]=a1.x; As[nb][akq+5][arow]=a1.y; As[nb][akq+6][arow]=a1.z; As[nb][akq+7][arow]=a1.w;
            *(float4*)&Bs[nb][bk][bn]    = b0;
            *(float4*)&Bs[nb][bk][bn+64] = b1;
            __syncthreads();
            buf = nb;
        }
    }
}

// =============================================================================
// double-buffered TT GEMM body: A and B both row-major K-contiguous
// =============================================================================
__device__ __forceinline__ void gemm_db_tt(
    const float* __restrict__ Abase, const float* __restrict__ Bbase, int K,
    float (* __restrict__ As)[16][132], float (* __restrict__ Bs)[16][132],
    int t, float acc[8][8])
{
    int row = t >> 1, kq = (t & 1) * 8;
    int tx = t & 15, ty = t >> 4;
    const float* Ap = Abase + (long)row * K + kq;
    const float* Bp = Bbase + (long)row * K + kq;

    float4 a0 = *(const float4*)(Ap);
    float4 a1 = *(const float4*)(Ap + 4);
    float4 b0 = *(const float4*)(Bp);
    float4 b1 = *(const float4*)(Bp + 4);
    As[0][kq+0][row]=a0.x; As[0][kq+1][row]=a0.y; As[0][kq+2][row]=a0.z; As[0][kq+3][row]=a0.w;
    As[0][kq+4][row]=a1.x; As[0][kq+5][row]=a1.y; As[0][kq+6][row]=a1.z; As[0][kq+7][row]=a1.w;
    Bs[0][kq+0][row]=b0.x; Bs[0][kq+1][row]=b0.y; Bs[0][kq+2][row]=b0.z; Bs[0][kq+3][row]=b0.w;
    Bs[0][kq+4][row]=b1.x; Bs[0][kq+5][row]=b1.y; Bs[0][kq+6][row]=b1.z; Bs[0][kq+7][row]=b1.w;
    __syncthreads();
    int buf = 0;
    for (int k0 = 16; k0 <= K; k0 += 16) {
        if (k0 < K) {
            a0 = *(const float4*)(Ap + k0);
            a1 = *(const float4*)(Ap + k0 + 4);
            b0 = *(const float4*)(Bp + k0);
            b1 = *(const float4*)(Bp + k0 + 4);
        }
        #pragma unroll
        for (int kk = 0; kk < 16; kk++) {
            float4 av0 = *(const float4*)&As[buf][kk][ty*4];
            float4 av1 = *(const float4*)&As[buf][kk][64+ty*4];
            float4 bv0 = *(const float4*)&Bs[buf][kk][tx*4];
            float4 bv1 = *(const float4*)&Bs[buf][kk][64+tx*4];
            float a8[8] = {av0.x,av0.y,av0.z,av0.w,av1.x,av1.y,av1.z,av1.w};
            float b8[8] = {bv0.x,bv0.y,bv0.z,bv0.w,bv1.x,bv1.y,bv1.z,bv1.w};
            #pragma unroll
            for (int i = 0; i < 8; i++)
                #pragma unroll
                for (int j = 0; j < 8; j++)
                    acc[i][j] += a8[i] * b8[j];
        }
        if (k0 < K) {
            int nb = buf ^ 1;
            As[nb][kq+0][row]=a0.x; As[nb][kq+1][row]=a0.y; As[nb][kq+2][row]=a0.z; As[nb][kq+3][row]=a0.w;
            As[nb][kq+4][row]=a1.x; As[nb][kq+5][row]=a1.y; As[nb][kq+6][row]=a1.z; As[nb][kq+7][row]=a1.w;
            Bs[nb][kq+0][row]=b0.x; Bs[nb][kq+1][row]=b0.y; Bs[nb][kq+2][row]=b0.z; Bs[nb][kq+3][row]=b0.w;
            Bs[nb][kq+4][row]=b1.x; Bs[nb][kq+5][row]=b1.y; Bs[nb][kq+6][row]=b1.z; Bs[nb][kq+7][row]=b1.w;
            __syncthreads();
            buf = nb;
        }
    }
}

__device__ __forceinline__ void gemm128_store(
    float* __restrict__ Crow, const float* __restrict__ bias,
    int t, float acc[8][8], long ldc)
{
    int tx = t & 15, ty = t >> 4;
    #pragma unroll
    for (int i = 0; i < 8; i++) {
        int m = (i < 4) ? (ty*4 + i) : (64 + ty*4 + i - 4);
        float bv = bias[m];
        float4 o0 = {acc[i][0]+bv, acc[i][1]+bv, acc[i][2]+bv, acc[i][3]+bv};
        float4 o1 = {acc[i][4]+bv, acc[i][5]+bv, acc[i][6]+bv, acc[i][7]+bv};
        *(float4*)&Crow[(long)m*ldc + tx*4]      = o0;
        *(float4*)&Crow[(long)m*ldc + 64 + tx*4] = o1;
    }
}

// stage A: [qk(256ch) | v(128ch)] = W * x ; grid (288, 3, BATCH)
__global__ void __launch_bounds__(256,2) gemm_stageA(
    const float* __restrict__ x,
    const float* __restrict__ qk_w, const float* __restrict__ qk_b,
    const float* __restrict__ v_w,  const float* __restrict__ v_b)
{
    int n0 = blockIdx.x * 128, y = blockIdx.y, b = blockIdx.z;
    int t = threadIdx.x;
    __shared__ float As[2][16][132];
    __shared__ float Bs[2][16][128];
    float acc[8][8] = {};
    const float* A   = (y < 2) ? (qk_w + (long)y*128*128) : v_w;
    const float* bia = (y < 2) ? (qk_b + y*128)           : v_b;
    int cch          = (y < 2) ? (y*128)                  : 256;
    gemm_db_conv(A, x + (long)b*128*HW2 + n0, 128, As, Bs, t, acc);
    gemm128_store(g_buf1 + ((long)b*384 + cch) * HW2 + n0, bia, t, acc, HW2);
}

// stage C: q2 + k2 ; grid (288, 4, BATCH)
__global__ void __launch_bounds__(256,2) gemm_stageC(
    const float* __restrict__ q2_w, const float* __restrict__ q2_b,
    const float* __restrict__ k2_w, const float* __restrict__ k2_b)
{
    int n0 = blockIdx.x * 128, y = blockIdx.y, b = blockIdx.z;
    int t = threadIdx.x;
    __shared__ float As[2][16][132];
    __shared__ float Bs[2][16][128];
    float acc[8][8] = {};
    const float* A   = (y < 2) ? (q2_w + (long)y*128*128) : (k2_w + (long)(y-2)*128*128);
    const float* bia = (y < 2) ? (q2_b + y*128)           : (k2_b + (y-2)*128);
    const float* Bbase = g_buf2 + ((long)b*384 + ((y < 2) ? 0 : 128)) * HW2 + n0;
    gemm_db_conv(A, Bbase, 128, As, Bs, t, acc);
    gemm128_store(g_buf3 + ((long)b*512 + y*128) * HW2 + n0, bia, t, acc, HW2);
}

// attention GEMM: attn = Q . K^T (temp folded into Q)
__global__ void __launch_bounds__(256,2) attn_gemm2(
    const float* __restrict__ kc, const float* __restrict__ knew)
{
    int z = blockIdx.z; int b = z / NFtot, f = z % NFtot;
    const float* Qp = g_qtok + (long)b * Ntok * D2;
    const float* Kp = (f < 2) ? (kc   + ((long)(b*2 + f)) * Ntok * D2)
                              : (knew + ((long)(b*2 + 1)) * Ntok * D2);
    int m0 = blockIdx.y * 128, n0 = blockIdx.x * 128;
    int t = threadIdx.x;
    int tx = t & 15, ty = t >> 4;
    __shared__ float As[2][16][132];
    __shared__ float Bs[2][16][132];
    float acc[8][8] = {};
    gemm_db_tt(Qp + (long)m0 * D2, Kp + (long)n0 * D2, D2, As, Bs, t, acc);
    float* Cp = g_attn + (long)z * Ntok * Ntok;
    #pragma unroll
    for (int i = 0; i < 8; i++) {
        int m = (i < 4) ? (ty*4 + i) : (64 + ty*4 + i - 4);
        float4 o0 = {acc[i][0], acc[i][1], acc[i][2], acc[i][3]};
        float4 o1 = {acc[i][4], acc[i][5], acc[i][6], acc[i][7]};
        *(float4*)&Cp[(long)(m0+m)*Ntok + n0 + tx*4]      = o0;
        *(float4*)&Cp[(long)(m0+m)*Ntok + n0 + 64 + tx*4] = o1;
    }
}

// proj 1x1 GEMM with fused window de-permute gather
__global__ void __launch_bounds__(256,2) proj_gemm2(
    const float* __restrict__ W, const float* __restrict__ bias,
    float* __restrict__ Out)
{
    int z  = blockIdx.z;
    int n0 = blockIdx.x * 128;
    int t = threadIdx.x;
    int tx = t & 15, ty = t >> 4;
    __shared__ float As[2][16][132];
    __shared__ float Bs[2][16][132];
    float acc[8][8] = {};
    int row = t >> 1;
    int p = n0 + row;
    int h = p / HWd, w = p % HWd;
    int token = (h % HGd) * HGd + (w % HGd);
    int vbase = ((h / HGd) * 4 + (w / HGd)) * 128;
    {
        int kq = (t & 1) * 8;
        const float* Ap = W + (long)row * 128 + kq;
        const float* Bp = g_otok + ((long)z * Ntok + token) * VDdim + vbase + kq;
        float4 a0 = *(const float4*)(Ap);
        float4 a1 = *(const float4*)(Ap + 4);
        float4 b0 = *(const float4*)(Bp);
        float4 b1 = *(const float4*)(Bp + 4);
        As[0][kq+0][row]=a0.x; As[0][kq+1][row]=a0.y; As[0][kq+2][row]=a0.z; As[0][kq+3][row]=a0.w;
        As[0][kq+4][row]=a1.x; As[0][kq+5][row]=a1.y; As[0][kq+6][row]=a1.z; As[0][kq+7][row]=a1.w;
        Bs[0][kq+0][row]=b0.x; Bs[0][kq+1][row]=b0.y; Bs[0][kq+2][row]=b0.z; Bs[0][kq+3][row]=b0.w;
        Bs[0][kq+4][row]=b1.x; Bs[0][kq+5][row]=b1.y; Bs[0][kq+6][row]=b1.z; Bs[0][kq+7][row]=b1.w;
        __syncthreads();
        int buf = 0;
        for (int k0 = 16; k0 <= 128; k0 += 16) {
            if (k0 < 128) {
                a0 = *(const float4*)(Ap + k0);
                a1 = *(const float4*)(Ap + k0 + 4);
                b0 = *(const float4*)(Bp + k0);
                b1 = *(const float4*)(Bp + k0 + 4);
            }
            #pragma unroll
            for (int kk = 0; kk < 16; kk++) {
                float4 av0 = *(const float4*)&As[buf][kk][ty*4];
                float4 av1 = *(const float4*)&As[buf][kk][64+ty*4];
                float4 bv0 = *(const float4*)&Bs[buf][kk][tx*4];
                float4 bv1 = *(const float4*)&Bs[buf][kk][64+tx*4];
                float a8[8] = {av0.x,av0.y,av0.z,av0.w,av1.x,av1.y,av1.z,av1.w};
                float b8[8] = {bv0.x,bv0.y,bv0.z,bv0.w,bv1.x,bv1.y,bv1.z,bv1.w};
                #pragma unroll
                for (int i = 0; i < 8; i++)
                    #pragma unroll
                    for (int j = 0; j < 8; j++)
                        acc[i][j] += a8[i] * b8[j];
            }
            if (k0 < 128) {
                int nb = buf ^ 1;
                As[nb][kq+0][row]=a0.x; As[nb][kq+1][row]=a0.y; As[nb][kq+2][row]=a0.z; As[nb][kq+3][row]=a0.w;
                As[nb][kq+4][row]=a1.x; As[nb][kq+5][row]=a1.y; As[nb][kq+6][row]=a1.z; As[nb][kq+7][row]=a1.w;
                Bs[nb][kq+0][row]=b0.x; Bs[nb][kq+1][row]=b0.y; Bs[nb][kq+2][row]=b0.z; Bs[nb][kq+3][row]=b0.w;
                Bs[nb][kq+4][row]=b1.x; Bs[nb][kq+5][row]=b1.y; Bs[nb][kq+6][row]=b1.z; Bs[nb][kq+7][row]=b1.w;
                __syncthreads();
                buf = nb;
            }
        }
    }
    #pragma unroll
    for (int i = 0; i < 8; i++) {
        int m = (i < 4) ? (ty*4 + i) : (64 + ty*4 + i - 4);
        float bv = bias[m];
        float4 o0 = {acc[i][0]+bv, acc[i][1]+bv, acc[i][2]+bv, acc[i][3]+bv};
        float4 o1 = {acc[i][4]+bv, acc[i][5]+bv, acc[i][6]+bv, acc[i][7]+bv};
        *(float4*)&Out[((long)z*128 + m)*HW2 + n0 + tx*4]      = o0;
        *(float4*)&Out[((long)z*128 + m)*HW2 + n0 + 64 + tx*4] = o1;
    }
}

// ---------------- depthwise 3x3 pad1 (on g_buf1 -> g_buf2) -------------------
__global__ void dw3x3(const float* __restrict__ qk_dw_w, const float* __restrict__ qk_dw_b,
                      const float* __restrict__ v_dw_w,  const float* __restrict__ v_dw_b)
{
    int idx = blockIdx.x * 256 + threadIdx.x;
    if (idx >= BATCH*384*HW2) return;
    int p  = idx % HW2;
    int ch = (idx / HW2) % 384;
    int b  = idx / (384*HW2);
    int h = p / HWd, w = p % HWd;
    const float* wgt; float bv;
    if (ch < 256) { wgt = qk_dw_w + ch*9;        bv = qk_dw_b[ch]; }
    else          { wgt = v_dw_w  + (ch-256)*9;  bv = v_dw_b[ch-256]; }
    const float* in = g_buf1 + ((long)(b*384 + ch)) * HW2;
    float s = bv;
    #pragma unroll
    for (int ky = 0; ky < 3; ky++) {
        int y = h + ky - 1;
        if ((unsigned)y >= (unsigned)HWd) continue;
        #pragma unroll
        for (int kx = 0; kx < 3; kx++) {
            int x = w + kx - 1;
            if ((unsigned)x >= (unsigned)HWd) continue;
            s += wgt[ky*3+kx] * in[y*HWd + x];
        }
    }
    g_buf2[idx] = s;
}

// ---------------- depthwise 4x4 stride4 pad1 (g_buf3 -> g_buf4) --------------
__global__ void dw4x4(const float* __restrict__ q2_dw_w, const float* __restrict__ q2_dw_b,
                      const float* __restrict__ k2_dw_w, const float* __restrict__ k2_dw_b)
{
    int idx = blockIdx.x * 256 + threadIdx.x;
    if (idx >= BATCH*512*Ntok) return;
    int t  = idx % Ntok;
    int ch = (idx / Ntok) % 512;
    int b  = idx / (512*Ntok);
    int oy = t / HGd, ox = t % HGd;
    const float* wgt; float bv;
    if (ch < 256) { wgt = q2_dw_w + ch*16;       bv = q2_dw_b[ch]; }
    else          { wgt = k2_dw_w + (ch-256)*16; bv = k2_dw_b[ch-256]; }
    const float* in = g_buf3 + ((long)(b*512 + ch)) * HW2;
    float s = bv;
    #pragma unroll
    for (int ky = 0; ky < 4; ky++) {
        int y = oy*4 - 1 + ky;
        if ((unsigned)y >= (unsigned)HWd) continue;
        #pragma unroll
        for (int kx = 0; kx < 4; kx++) {
            int x = ox*4 - 1 + kx;
            if ((unsigned)x >= (unsigned)HWd) continue;
            s += wgt[ky*4+kx] * in[y*HWd + x];
        }
    }
    g_buf4[idx] = s;
}

// ---------------- l2 normalize + token-major q/k (temp folded into q) --------
__global__ void __launch_bounds__(256) norm_qk(float* __restrict__ kout,
                                               const float* __restrict__ temp)
{
    int token = blockIdx.x, b = blockIdx.y, d = threadIdx.x;
    float qv = g_buf4[((long)b*512 + d)       * Ntok + token];
    float kv = g_buf4[((long)b*512 + 256 + d) * Ntok + token];
    __shared__ float red[256];
    __shared__ float qinv_s, kinv_s;
    red[d] = qv*qv; __syncthreads();
    for (int s = 128; s > 0; s >>= 1) { if (d < s) red[d] += red[d+s]; __syncthreads(); }
    if (d == 0) qinv_s = (*temp) / fmaxf(sqrtf(red[0]), 1e-12f);
    __syncthreads();
    red[d] = kv*kv; __syncthreads();
    for (int s = 128; s > 0; s >>= 1) { if (d < s) red[d] += red[d+s]; __syncthreads(); }
    if (d == 0) kinv_s = 1.f / fmaxf(sqrtf(red[0]), 1e-12f);
    __syncthreads();
    g_qtok[((long)b*Ntok + token) * D2 + d] = qv * qinv_s;
    kout  [((long)(b*2 + 1)*Ntok + token) * D2 + d] = kv * kinv_s;
}

// ---------------- build v_new (strided-window permute) into d_out ------------
__global__ void build_vnew(float* __restrict__ vout)
{
    int idx = blockIdx.x * 256 + threadIdx.x;
    if (idx >= BATCH*Ntok*VDdim) return;
    int vd    = idx % VDdim;
    int token = (idx / VDdim) % Ntok;
    int b     = idx / (Ntok*VDdim);
    int c  = vd & 127;
    int p2 = (vd >> 7) & 3;
    int p1 = vd >> 9;
    int hi = token / HGd, wi = token % HGd;
    float val = g_buf2[((long)(b*384 + 256 + c)) * HW2 + (p1*HGd + hi) * HWd + (p2*HGd + wi)];
    vout[((long)(b*2 + 1)*Ntok + token) * VDdim + vd] = val;
}

// =============================================================================
// fused top-k + local-mask sparse softmax + sparse AV (attn row cached in smem)
// =============================================================================
__global__ void __launch_bounds__(256) sparse_attn_av(
    const float* __restrict__ v_cached, const float* __restrict__ vout)
{
    int n = blockIdx.x, f = blockIdx.y, b = blockIdx.z;
    const float* arow = g_attn + ((long)(b*NFtot + f) * Ntok + n) * Ntok;
    int tid = threadIdx.x;

    __shared__ float rowbuf[Ntok];
    for (int m = tid*4; m < Ntok; m += 1024)
        *(float4*)&rowbuf[m] = *(const float4*)&arow[m];
    __syncthreads();

    // pass 1: per-thread top-5
    float t5[5] = {-INFINITY,-INFINITY,-INFINITY,-INFINITY,-INFINITY};
    for (int m = tid; m < Ntok; m += 256) {
        float v = rowbuf[m];
        if (v > t5[4]) {
            t5[4] = v;
            #pragma unroll
            for (int i = 4; i > 0; i--)
                if (t5[i] > t5[i-1]) { float tmp = t5[i-1]; t5[i-1] = t5[i]; t5[i] = tmp; }
        }
    }
    __shared__ float cand[256*5];
    __shared__ float red[256];
    #pragma unroll
    for (int i = 0; i < 5; i++) cand[tid*5 + i] = t5[i];
    __syncthreads();

    float thr = INFINITY;
    for (int r = 0; r < 5; r++) {
        float lm = -INFINITY;
        #pragma unroll
        for (int i = 0; i < 5; i++) {
            float v = cand[tid*5 + i];
            if (v < thr && v > lm) lm = v;
        }
        red[tid] = lm; __syncthreads();
        for (int s = 128; s > 0; s >>= 1) { if (tid < s) red[tid] = fmaxf(red[tid], red[tid+s]); __syncthreads(); }
        thr = red[0];
        __syncthreads();
    }
    float kth = thr;

    // pass 2: collect nonzero entries of attn*(1[>=kth] + 1[local])
    __shared__ int   nnz;
    __shared__ int   sidx[LISTCAP];
    __shared__ float sval[LISTCAP];
    if (tid == 0) nnz = 0;
    __syncthreads();
    int ny = n / HGd, nx = n % HGd;
    for (int m = tid; m < Ntok; m += 256) {
        float a = rowbuf[m];
        float coef = (a >= kth) ? 1.f : 0.f;
        int my = m / HGd, mx = m % HGd;
        if (abs(ny - my) + abs(nx - mx) <= 4) coef += 1.f;
        float v = a * coef;
        if (v != 0.f) {
            int pos = atomicAdd(&nnz, 1);
            if (pos < LISTCAP) { sidx[pos] = m; sval[pos] = v; }
        }
    }
    __syncthreads();
    int cnt = min(nnz, LISTCAP);

    __shared__ float smax, ssum;
    if (tid == 0) {
        float mx = -INFINITY;
        for (int e = 0; e < cnt; e++) mx = fmaxf(mx, sval[e]);
        smax = mx;
    }
    __syncthreads();
    if (tid < cnt) sval[tid] = expf(sval[tid] - smax);
    __syncthreads();
    if (tid == 0) {
        float s = 0.f;
        for (int e = 0; e < cnt; e++) s += sval[e];
        ssum = s;
    }
    __syncthreads();
    // normalize in place (weights pre-divided -> no FMUL in AV loop)
    if (tid < cnt) sval[tid] = sval[tid] / ssum;
    __syncthreads();

    // sparse AV: each thread owns 8 contiguous vd dims
    const float* vbase = (f < 2) ? (v_cached + ((long)(b*2 + f)) * Ntok * VDdim)
                                 : (vout     + ((long)(b*2 + 1)) * Ntok * VDdim);
    float* orow = g_otok + ((long)(b*NFtot + f) * Ntok + n) * VDdim;
    int d0 = tid * 8;
    float acc[8] = {};
    int e = 0;
    for (; e + 2 <= cnt; e += 2) {
        float w0 = sval[e];
        float w1 = sval[e+1];
        const float* vr0 = vbase + (long)sidx[e]   * VDdim + d0;
        const float* vr1 = vbase + (long)sidx[e+1] * VDdim + d0;
        float4 a0 = *(const float4*)vr0;
        float4 a1 = *(const float4*)(vr0 + 4);
        float4 c0 = *(const float4*)vr1;
        float4 c1 = *(const float4*)(vr1 + 4);
        acc[0] += w0*a0.x + w1*c0.x; acc[1] += w0*a0.y + w1*c0.y;
        acc[2] += w0*a0.z + w1*c0.z; acc[3] += w0*a0.w + w1*c0.w;
        acc[4] += w0*a1.x + w1*c1.x; acc[5] += w0*a1.y + w1*c1.y;
        acc[6] += w0*a1.z + w1*c1.z; acc[7] += w0*a1.w + w1*c1.w;
    }
    for (; e < cnt; e++) {
        float w = sval[e];
        const float* vr = vbase + (long)sidx[e] * VDdim + d0;
        float4 v0 = *(const float4*)vr;
        float4 v1 = *(const float4*)(vr + 4);
        acc[0] += w*v0.x; acc[1] += w*v0.y; acc[2] += w*v0.z; acc[3] += w*v0.w;
        acc[4] += w*v1.x; acc[5] += w*v1.y; acc[6] += w*v1.z; acc[7] += w*v1.w;
    }
    float4 o0 = {acc[0],acc[1],acc[2],acc[3]};
    float4 o1 = {acc[4],acc[5],acc[6],acc[7]};
    *reinterpret_cast<float4*>(orow + d0)     = o0;
    *reinterpret_cast<float4*>(orow + d0 + 4) = o1;
}

// ---------------------------------- launch -----------------------------------
extern "C" void kernel_launch(void* const* d_in, const int* in_sizes, int n_in,
                              void* d_out, int out_size)
{
    (void)in_sizes; (void)n_in; (void)out_size;
    const float* x         = (const float*)d_in[0];
    const float* k_cached  = (const float*)d_in[1];
    const float* v_cached  = (const float*)d_in[2];
    const float* temperature = (const float*)d_in[3];
    const float* qk_w  = (const float*)d_in[4],  *qk_b  = (const float*)d_in[5];
    const float* qk_dw_w = (const float*)d_in[6], *qk_dw_b = (const float*)d_in[7];
    const float* v_w   = (const float*)d_in[8],  *v_b   = (const float*)d_in[9];
    const float* v_dw_w = (const float*)d_in[10], *v_dw_b = (const float*)d_in[11];
    const float* k2_w  = (const float*)d_in[12], *k2_b  = (const float*)d_in[13];
    const float* k2_dw_w = (const float*)d_in[14], *k2_dw_b = (const float*)d_in[15];
    const float* q2_w  = (const float*)d_in[16], *q2_b  = (const float*)d_in[17];
    const float* q2_dw_w = (const float*)d_in[18], *q2_dw_b = (const float*)d_in[19];
    const float* proj_w = (const float*)d_in[20], *proj_b = (const float*)d_in[21];

    float* out = (float*)d_out;
    const long OUT_K = (long)BATCH * NFtot * 128 * HW2;
    const long OUT_V = OUT_K + (long)BATCH * 2 * Ntok * D2;
    float* kout = out + OUT_K;
    float* vout = out + OUT_V;

    dim3 blk(256);

    gemm_stageA<<<dim3(288,3,BATCH), blk>>>(x, qk_w, qk_b, v_w, v_b);
    dw3x3<<<(BATCH*384*HW2 + 255)/256, blk>>>(qk_dw_w, qk_dw_b, v_dw_w, v_dw_b);
    gemm_stageC<<<dim3(288,4,BATCH), blk>>>(q2_w, q2_b, k2_w, k2_b);
    dw4x4<<<(BATCH*512*Ntok + 255)/256, blk>>>(q2_dw_w, q2_dw_b, k2_dw_w, k2_dw_b);
    norm_qk<<<dim3(Ntok, BATCH), blk>>>(kout, temperature);
    build_vnew<<<(BATCH*Ntok*VDdim + 255)/256, blk>>>(vout);
    for (int b = 0; b < BATCH; b++) {
        cudaMemcpyAsync(kout + (long)(b*2)*Ntok*D2,
                        k_cached + (long)(b*2+1)*Ntok*D2,
                        (size_t)Ntok*D2*sizeof(float), cudaMemcpyDeviceToDevice, 0);
        cudaMemcpyAsync(vout + (long)(b*2)*Ntok*VDdim,
                        v_cached + (long)(b*2+1)*Ntok*VDdim,
                        (size_t)Ntok*VDdim*sizeof(float), cudaMemcpyDeviceToDevice, 0);
    }
    attn_gemm2<<<dim3(18,18,BATCH*NFtot), blk>>>(k_cached, kout);
    sparse_attn_av<<<dim3(Ntok, NFtot, BATCH), blk>>>(v_cached, vout);
    proj_gemm2<<<dim3(288,1,BATCH*NFtot), blk>>>(proj_w, proj_b, out);
}

// round 7
// speedup vs baseline: 1.2499x; 1.0593x over previous
#include <cuda_runtime.h>
#include <math.h>

#define BATCH 2
#define HWd   192
#define HW2   (HWd*HWd)      // 36864
#define HGd   48
#define Ntok  (HGd*HGd)      // 2304
#define D2    256
#define VDdim 2048
#define NFtot 3
#define LISTCAP 128

typedef unsigned long long u64;

// ---------------- scratch (device globals; no allocs allowed) ----------------
__device__ float g_buf1[(size_t)BATCH*384*HW2];
__device__ float g_buf2[(size_t)BATCH*384*HW2];
__device__ float g_buf3[(size_t)BATCH*512*HW2];
__device__ float g_buf4[(size_t)BATCH*512*Ntok];
__device__ float g_qtok[(size_t)BATCH*Ntok*D2];
__device__ float g_attn[(size_t)BATCH*NFtot*Ntok*Ntok];
__device__ float g_otok[(size_t)BATCH*NFtot*Ntok*VDdim];

// ---------------- packed fp32x2 primitives (Blackwell FFMA2) -----------------
__device__ __forceinline__ u64 dup2(float x) {
    u64 r;
    asm("mov.b64 %0, {%1, %1};" : "=l"(r) : "r"(__float_as_uint(x)));
    return r;
}
__device__ __forceinline__ void fma2(u64 &d, u64 a, u64 b) {
    asm("fma.rn.f32x2 %0, %1, %2, %3;" : "=l"(d) : "l"(a), "l"(b), "l"(d));
}
__device__ __forceinline__ float2 unpk(u64 v) {
    float lo, hi;
    asm("mov.b64 {%0, %1}, %2;" : "=f"(lo), "=f"(hi) : "l"(v));
    return make_float2(lo, hi);
}

// one k-step of the 8x8 fragment: 32 fma.f32x2 = 64 FLOP-pairs
__device__ __forceinline__ void fma_step(
    const float* __restrict__ As_k, const float* __restrict__ Bs_k,
    int tx, int ty, u64 acc[8][4])
{
    float4 av0 = *(const float4*)(As_k + ty*4);
    float4 av1 = *(const float4*)(As_k + 64 + ty*4);
    ulonglong2 bv0 = *(const ulonglong2*)(Bs_k + tx*4);
    ulonglong2 bv1 = *(const ulonglong2*)(Bs_k + 64 + tx*4);
    u64 aa[8] = {dup2(av0.x), dup2(av0.y), dup2(av0.z), dup2(av0.w),
                 dup2(av1.x), dup2(av1.y), dup2(av1.z), dup2(av1.w)};
    u64 bb[4] = {bv0.x, bv0.y, bv1.x, bv1.y};
    #pragma unroll
    for (int i = 0; i < 8; i++) {
        fma2(acc[i][0], aa[i], bb[0]);
        fma2(acc[i][1], aa[i], bb[1]);
        fma2(acc[i][2], aa[i], bb[2]);
        fma2(acc[i][3], aa[i], bb[3]);
    }
}

// =============================================================================
// double-buffered conv GEMM body: A[128 x K] (row stride K), B (rows stride HW2)
// =============================================================================
__device__ __forceinline__ void gemm_db_conv(
    const float* __restrict__ A, const float* __restrict__ Bbase, int K,
    float (* __restrict__ As)[16][132], float (* __restrict__ Bs)[16][128],
    int t, u64 acc[8][4][4])   // unused dims collapsed by caller
{
}

__device__ __forceinline__ void gemm_db_conv2(
    const float* __restrict__ A, const float* __restrict__ Bbase, int K,
    float (* __restrict__ As)[16][132], float (* __restrict__ Bs)[16][128],
    int t, u64 acc[8][4])
{
    int arow = t >> 1, akq = (t & 1) * 8;
    int bk = t >> 4, bn = (t & 15) * 4;
    int tx = t & 15, ty = t >> 4;
    const float* Ap = A + (long)arow * K + akq;

    float4 a0 = *(const float4*)(Ap);
    float4 a1 = *(const float4*)(Ap + 4);
    const float* bs0 = Bbase + (long)bk * HW2;
    float4 b0 = *(const float4*)(bs0 + bn);
    float4 b1 = *(const float4*)(bs0 + bn + 64);
    As[0][akq+0][arow]=a0.x; As[0][akq+1][arow]=a0.y; As[0][akq+2][arow]=a0.z; As[0][akq+3][arow]=a0.w;
    As[0][akq+4][arow]=a1.x; As[0][akq+5][arow]=a1.y; As[0][akq+6][arow]=a1.z; As[0][akq+7][arow]=a1.w;
    *(float4*)&Bs[0][bk][bn]    = b0;
    *(float4*)&Bs[0][bk][bn+64] = b1;
    __syncthreads();
    int buf = 0;
    for (int k0 = 16; k0 <= K; k0 += 16) {
        if (k0 < K) {
            a0 = *(const float4*)(Ap + k0);
            a1 = *(const float4*)(Ap + k0 + 4);
            const float* bs2 = Bbase + (long)(k0 + bk) * HW2;
            b0 = *(const float4*)(bs2 + bn);
            b1 = *(const float4*)(bs2 + bn + 64);
        }
        #pragma unroll
        for (int kk = 0; kk < 16; kk++)
            fma_step(&As[buf][kk][0], &Bs[buf][kk][0], tx, ty, acc);
        if (k0 < K) {
            int nb = buf ^ 1;
            As[nb][akq+0][arow]=a0.x; As[nb][akq+1][arow]=a0.y; As[nb][akq+2][arow]=a0.z; As[nb][akq+3][arow]=a0.w;
            As[nb][akq+4][arow]=a1.x; As[nb][akq+5][arow]=a1.y; As[nb][akq+6][arow]=a1.z; As[nb][akq+7][arow]=a1.w;
            *(float4*)&Bs[nb][bk][bn]    = b0;
            *(float4*)&Bs[nb][bk][bn+64] = b1;
            __syncthreads();
            buf = nb;
        }
    }
}

// =============================================================================
// double-buffered TT GEMM body: A and B both row-major K-contiguous
// =============================================================================
__device__ __forceinline__ void gemm_db_tt2(
    const float* __restrict__ Abase, const float* __restrict__ Bbase, int K,
    float (* __restrict__ As)[16][132], float (* __restrict__ Bs)[16][132],
    int t, u64 acc[8][4])
{
    int row = t >> 1, kq = (t & 1) * 8;
    int tx = t & 15, ty = t >> 4;
    const float* Ap = Abase + (long)row * K + kq;
    const float* Bp = Bbase + (long)row * K + kq;

    float4 a0 = *(const float4*)(Ap);
    float4 a1 = *(const float4*)(Ap + 4);
    float4 b0 = *(const float4*)(Bp);
    float4 b1 = *(const float4*)(Bp + 4);
    As[0][kq+0][row]=a0.x; As[0][kq+1][row]=a0.y; As[0][kq+2][row]=a0.z; As[0][kq+3][row]=a0.w;
    As[0][kq+4][row]=a1.x; As[0][kq+5][row]=a1.y; As[0][kq+6][row]=a1.z; As[0][kq+7][row]=a1.w;
    Bs[0][kq+0][row]=b0.x; Bs[0][kq+1][row]=b0.y; Bs[0][kq+2][row]=b0.z; Bs[0][kq+3][row]=b0.w;
    Bs[0][kq+4][row]=b1.x; Bs[0][kq+5][row]=b1.y; Bs[0][kq+6][row]=b1.z; Bs[0][kq+7][row]=b1.w;
    __syncthreads();
    int buf = 0;
    for (int k0 = 16; k0 <= K; k0 += 16) {
        if (k0 < K) {
            a0 = *(const float4*)(Ap + k0);
            a1 = *(const float4*)(Ap + k0 + 4);
            b0 = *(const float4*)(Bp + k0);
            b1 = *(const float4*)(Bp + k0 + 4);
        }
        #pragma unroll
        for (int kk = 0; kk < 16; kk++)
            fma_step(&As[buf][kk][0], &Bs[buf][kk][0], tx, ty, acc);
        if (k0 < K) {
            int nb = buf ^ 1;
            As[nb][kq+0][row]=a0.x; As[nb][kq+1][row]=a0.y; As[nb][kq+2][row]=a0.z; As[nb][kq+3][row]=a0.w;
            As[nb][kq+4][row]=a1.x; As[nb][kq+5][row]=a1.y; As[nb][kq+6][row]=a1.z; As[nb][kq+7][row]=a1.w;
            Bs[nb][kq+0][row]=b0.x; Bs[nb][kq+1][row]=b0.y; Bs[nb][kq+2][row]=b0.z; Bs[nb][kq+3][row]=b0.w;
            Bs[nb][kq+4][row]=b1.x; Bs[nb][kq+5][row]=b1.y; Bs[nb][kq+6][row]=b1.z; Bs[nb][kq+7][row]=b1.w;
            __syncthreads();
            buf = nb;
        }
    }
}

__device__ __forceinline__ void gemm128_store2(
    float* __restrict__ Crow, const float* __restrict__ bias,
    int t, u64 acc[8][4], long ldc)
{
    int tx = t & 15, ty = t >> 4;
    #pragma unroll
    for (int i = 0; i < 8; i++) {
        int m = (i < 4) ? (ty*4 + i) : (64 + ty*4 + i - 4);
        float bv = bias ? bias[m] : 0.f;
        float2 p0 = unpk(acc[i][0]), p1 = unpk(acc[i][1]);
        float2 p2 = unpk(acc[i][2]), p3 = unpk(acc[i][3]);
        float4 o0 = {p0.x+bv, p0.y+bv, p1.x+bv, p1.y+bv};
        float4 o1 = {p2.x+bv, p2.y+bv, p3.x+bv, p3.y+bv};
        *(float4*)&Crow[(long)m*ldc + tx*4]      = o0;
        *(float4*)&Crow[(long)m*ldc + 64 + tx*4] = o1;
    }
}

// stage A: [qk(256ch) | v(128ch)] = W * x ; grid (288, 3, BATCH)
__global__ void __launch_bounds__(256,2) gemm_stageA(
    const float* __restrict__ x,
    const float* __restrict__ qk_w, const float* __restrict__ qk_b,
    const float* __restrict__ v_w,  const float* __restrict__ v_b)
{
    int n0 = blockIdx.x * 128, y = blockIdx.y, b = blockIdx.z;
    int t = threadIdx.x;
    __shared__ float As[2][16][132];
    __shared__ float Bs[2][16][128];
    u64 acc[8][4] = {};
    const float* A   = (y < 2) ? (qk_w + (long)y*128*128) : v_w;
    const float* bia = (y < 2) ? (qk_b + y*128)           : v_b;
    int cch          = (y < 2) ? (y*128)                  : 256;
    gemm_db_conv2(A, x + (long)b*128*HW2 + n0, 128, As, Bs, t, acc);
    gemm128_store2(g_buf1 + ((long)b*384 + cch) * HW2 + n0, bia, t, acc, HW2);
}

// stage C: q2 + k2 ; grid (288, 4, BATCH)
__global__ void __launch_bounds__(256,2) gemm_stageC(
    const float* __restrict__ q2_w, const float* __restrict__ q2_b,
    const float* __restrict__ k2_w, const float* __restrict__ k2_b)
{
    int n0 = blockIdx.x * 128, y = blockIdx.y, b = blockIdx.z;
    int t = threadIdx.x;
    __shared__ float As[2][16][132];
    __shared__ float Bs[2][16][128];
    u64 acc[8][4] = {};
    const float* A   = (y < 2) ? (q2_w + (long)y*128*128) : (k2_w + (long)(y-2)*128*128);
    const float* bia = (y < 2) ? (q2_b + y*128)           : (k2_b + (y-2)*128);
    const float* Bbase = g_buf2 + ((long)b*384 + ((y < 2) ? 0 : 128)) * HW2 + n0;
    gemm_db_conv2(A, Bbase, 128, As, Bs, t, acc);
    gemm128_store2(g_buf3 + ((long)b*512 + y*128) * HW2 + n0, bia, t, acc, HW2);
}

// attention GEMM: attn = Q . K^T (temp folded into Q)
__global__ void __launch_bounds__(256,2) attn_gemm2(
    const float* __restrict__ kc, const float* __restrict__ knew)
{
    int z = blockIdx.z; int b = z / NFtot, f = z % NFtot;
    const float* Qp = g_qtok + (long)b * Ntok * D2;
    const float* Kp = (f < 2) ? (kc   + ((long)(b*2 + f)) * Ntok * D2)
                              : (knew + ((long)(b*2 + 1)) * Ntok * D2);
    int m0 = blockIdx.y * 128, n0 = blockIdx.x * 128;
    int t = threadIdx.x;
    int tx = t & 15, ty = t >> 4;
    __shared__ float As[2][16][132];
    __shared__ float Bs[2][16][132];
    u64 acc[8][4] = {};
    gemm_db_tt2(Qp + (long)m0 * D2, Kp + (long)n0 * D2, D2, As, Bs, t, acc);
    float* Cp = g_attn + (long)z * Ntok * Ntok;
    #pragma unroll
    for (int i = 0; i < 8; i++) {
        int m = (i < 4) ? (ty*4 + i) : (64 + ty*4 + i - 4);
        float2 p0 = unpk(acc[i][0]), p1 = unpk(acc[i][1]);
        float2 p2 = unpk(acc[i][2]), p3 = unpk(acc[i][3]);
        float4 o0 = {p0.x, p0.y, p1.x, p1.y};
        float4 o1 = {p2.x, p2.y, p3.x, p3.y};
        *(float4*)&Cp[(long)(m0+m)*Ntok + n0 + tx*4]      = o0;
        *(float4*)&Cp[(long)(m0+m)*Ntok + n0 + 64 + tx*4] = o1;
    }
}

// proj 1x1 GEMM with fused window de-permute gather
__global__ void __launch_bounds__(256,2) proj_gemm2(
    const float* __restrict__ W, const float* __restrict__ bias,
    float* __restrict__ Out)
{
    int z  = blockIdx.z;
    int n0 = blockIdx.x * 128;
    int t = threadIdx.x;
    int tx = t & 15, ty = t >> 4;
    __shared__ float As[2][16][132];
    __shared__ float Bs[2][16][132];
    u64 acc[8][4] = {};
    int row = t >> 1;
    int p = n0 + row;
    int h = p / HWd, w = p % HWd;
    int token = (h % HGd) * HGd + (w % HGd);
    int vbase = ((h / HGd) * 4 + (w / HGd)) * 128;
    {
        int kq = (t & 1) * 8;
        const float* Ap = W + (long)row * 128 + kq;
        const float* Bp = g_otok + ((long)z * Ntok + token) * VDdim + vbase + kq;
        float4 a0 = *(const float4*)(Ap);
        float4 a1 = *(const float4*)(Ap + 4);
        float4 b0 = *(const float4*)(Bp);
        float4 b1 = *(const float4*)(Bp + 4);
        As[0][kq+0][row]=a0.x; As[0][kq+1][row]=a0.y; As[0][kq+2][row]=a0.z; As[0][kq+3][row]=a0.w;
        As[0][kq+4][row]=a1.x; As[0][kq+5][row]=a1.y; As[0][kq+6][row]=a1.z; As[0][kq+7][row]=a1.w;
        Bs[0][kq+0][row]=b0.x; Bs[0][kq+1][row]=b0.y; Bs[0][kq+2][row]=b0.z; Bs[0][kq+3][row]=b0.w;
        Bs[0][kq+4][row]=b1.x; Bs[0][kq+5][row]=b1.y; Bs[0][kq+6][row]=b1.z; Bs[0][kq+7][row]=b1.w;
        __syncthreads();
        int buf = 0;
        for (int k0 = 16; k0 <= 128; k0 += 16) {
            if (k0 < 128) {
                a0 = *(const float4*)(Ap + k0);
                a1 = *(const float4*)(Ap + k0 + 4);
                b0 = *(const float4*)(Bp + k0);
                b1 = *(const float4*)(Bp + k0 + 4);
            }
            #pragma unroll
            for (int kk = 0; kk < 16; kk++)
                fma_step(&As[buf][kk][0], &Bs[buf][kk][0], tx, ty, acc);
            if (k0 < 128) {
                int nb = buf ^ 1;
                As[nb][kq+0][row]=a0.x; As[nb][kq+1][row]=a0.y; As[nb][kq+2][row]=a0.z; As[nb][kq+3][row]=a0.w;
                As[nb][kq+4][row]=a1.x; As[nb][kq+5][row]=a1.y; As[nb][kq+6][row]=a1.z; As[nb][kq+7][row]=a1.w;
                Bs[nb][kq+0][row]=b0.x; Bs[nb][kq+1][row]=b0.y; Bs[nb][kq+2][row]=b0.z; Bs[nb][kq+3][row]=b0.w;
                Bs[nb][kq+4][row]=b1.x; Bs[nb][kq+5][row]=b1.y; Bs[nb][kq+6][row]=b1.z; Bs[nb][kq+7][row]=b1.w;
                __syncthreads();
                buf = nb;
            }
        }
    }
    #pragma unroll
    for (int i = 0; i < 8; i++) {
        int m = (i < 4) ? (ty*4 + i) : (64 + ty*4 + i - 4);
        float bv = bias[m];
        float2 p0 = unpk(acc[i][0]), p1 = unpk(acc[i][1]);
        float2 p2 = unpk(acc[i][2]), p3 = unpk(acc[i][3]);
        float4 o0 = {p0.x+bv, p0.y+bv, p1.x+bv, p1.y+bv};
        float4 o1 = {p2.x+bv, p2.y+bv, p3.x+bv, p3.y+bv};
        *(float4*)&Out[((long)z*128 + m)*HW2 + n0 + tx*4]      = o0;
        *(float4*)&Out[((long)z*128 + m)*HW2 + n0 + 64 + tx*4] = o1;
    }
}

// ---------------- depthwise 3x3 pad1 (on g_buf1 -> g_buf2) -------------------
__global__ void dw3x3(const float* __restrict__ qk_dw_w, const float* __restrict__ qk_dw_b,
                      const float* __restrict__ v_dw_w,  const float* __restrict__ v_dw_b)
{
    int idx = blockIdx.x * 256 + threadIdx.x;
    if (idx >= BATCH*384*HW2) return;
    int p  = idx % HW2;
    int ch = (idx / HW2) % 384;
    int b  = idx / (384*HW2);
    int h = p / HWd, w = p % HWd;
    const float* wgt; float bv;
    if (ch < 256) { wgt = qk_dw_w + ch*9;        bv = qk_dw_b[ch]; }
    else          { wgt = v_dw_w  + (ch-256)*9;  bv = v_dw_b[ch-256]; }
    const float* in = g_buf1 + ((long)(b*384 + ch)) * HW2;
    float s = bv;
    #pragma unroll
    for (int ky = 0; ky < 3; ky++) {
        int y = h + ky - 1;
        if ((unsigned)y >= (unsigned)HWd) continue;
        #pragma unroll
        for (int kx = 0; kx < 3; kx++) {
            int x = w + kx - 1;
            if ((unsigned)x >= (unsigned)HWd) continue;
            s += wgt[ky*3+kx] * in[y*HWd + x];
        }
    }
    g_buf2[idx] = s;
}

// ---------------- depthwise 4x4 stride4 pad1 (g_buf3 -> g_buf4) --------------
__global__ void dw4x4(const float* __restrict__ q2_dw_w, const float* __restrict__ q2_dw_b,
                      const float* __restrict__ k2_dw_w, const float* __restrict__ k2_dw_b)
{
    int idx = blockIdx.x * 256 + threadIdx.x;
    if (idx >= BATCH*512*Ntok) return;
    int t  = idx % Ntok;
    int ch = (idx / Ntok) % 512;
    int b  = idx / (512*Ntok);
    int oy = t / HGd, ox = t % HGd;
    const float* wgt; float bv;
    if (ch < 256) { wgt = q2_dw_w + ch*16;       bv = q2_dw_b[ch]; }
    else          { wgt = k2_dw_w + (ch-256)*16; bv = k2_dw_b[ch-256]; }
    const float* in = g_buf3 + ((long)(b*512 + ch)) * HW2;
    float s = bv;
    #pragma unroll
    for (int ky = 0; ky < 4; ky++) {
        int y = oy*4 - 1 + ky;
        if ((unsigned)y >= (unsigned)HWd) continue;
        #pragma unroll
        for (int kx = 0; kx < 4; kx++) {
            int x = ox*4 - 1 + kx;
            if ((unsigned)x >= (unsigned)HWd) continue;
            s += wgt[ky*4+kx] * in[y*HWd + x];
        }
    }
    g_buf4[idx] = s;
}

// ---------------- l2 normalize + token-major q/k (temp folded into q) --------
__global__ void __launch_bounds__(256) norm_qk(float* __restrict__ kout,
                                               const float* __restrict__ temp)
{
    int token = blockIdx.x, b = blockIdx.y, d = threadIdx.x;
    float qv = g_buf4[((long)b*512 + d)       * Ntok + token];
    float kv = g_buf4[((long)b*512 + 256 + d) * Ntok + token];
    __shared__ float red[256];
    __shared__ float qinv_s, kinv_s;
    red[d] = qv*qv; __syncthreads();
    for (int s = 128; s > 0; s >>= 1) { if (d < s) red[d] += red[d+s]; __syncthreads(); }
    if (d == 0) qinv_s = (*temp) / fmaxf(sqrtf(red[0]), 1e-12f);
    __syncthreads();
    red[d] = kv*kv; __syncthreads();
    for (int s = 128; s > 0; s >>= 1) { if (d < s) red[d] += red[d+s]; __syncthreads(); }
    if (d == 0) kinv_s = 1.f / fmaxf(sqrtf(red[0]), 1e-12f);
    __syncthreads();
    g_qtok[((long)b*Ntok + token) * D2 + d] = qv * qinv_s;
    kout  [((long)(b*2 + 1)*Ntok + token) * D2 + d] = kv * kinv_s;
}

// ---------------- build v_new (strided-window permute) into d_out ------------
__global__ void build_vnew(float* __restrict__ vout)
{
    int idx = blockIdx.x * 256 + threadIdx.x;
    if (idx >= BATCH*Ntok*VDdim) return;
    int vd    = idx % VDdim;
    int token = (idx / VDdim) % Ntok;
    int b     = idx / (Ntok*VDdim);
    int c  = vd & 127;
    int p2 = (vd >> 7) & 3;
    int p1 = vd >> 9;
    int hi = token / HGd, wi = token % HGd;
    float val = g_buf2[((long)(b*384 + 256 + c)) * HW2 + (p1*HGd + hi) * HWd + (p2*HGd + wi)];
    vout[((long)(b*2 + 1)*Ntok + token) * VDdim + vd] = val;
}

// =============================================================================
// fused top-k + local-mask sparse softmax + sparse AV (attn row cached in smem)
// =============================================================================
__global__ void __launch_bounds__(256) sparse_attn_av(
    const float* __restrict__ v_cached, const float* __restrict__ vout)
{
    int n = blockIdx.x, f = blockIdx.y, b = blockIdx.z;
    const float* arow = g_attn + ((long)(b*NFtot + f) * Ntok + n) * Ntok;
    int tid = threadIdx.x;

    __shared__ float rowbuf[Ntok];
    for (int m = tid*4; m < Ntok; m += 1024)
        *(float4*)&rowbuf[m] = *(const float4*)&arow[m];
    __syncthreads();

    // pass 1: per-thread top-5
    float t5[5] = {-INFINITY,-INFINITY,-INFINITY,-INFINITY,-INFINITY};
    for (int m = tid; m < Ntok; m += 256) {
        float v = rowbuf[m];
        if (v > t5[4]) {
            t5[4] = v;
            #pragma unroll
            for (int i = 4; i > 0; i--)
                if (t5[i] > t5[i-1]) { float tmp = t5[i-1]; t5[i-1] = t5[i]; t5[i] = tmp; }
        }
    }
    __shared__ float cand[256*5];
    __shared__ float red[256];
    #pragma unroll
    for (int i = 0; i < 5; i++) cand[tid*5 + i] = t5[i];
    __syncthreads();

    float thr = INFINITY;
    for (int r = 0; r < 5; r++) {
        float lm = -INFINITY;
        #pragma unroll
        for (int i = 0; i < 5; i++) {
            float v = cand[tid*5 + i];
            if (v < thr && v > lm) lm = v;
        }
        red[tid] = lm; __syncthreads();
        for (int s = 128; s > 0; s >>= 1) { if (tid < s) red[tid] = fmaxf(red[tid], red[tid+s]); __syncthreads(); }
        thr = red[0];
        __syncthreads();
    }
    float kth = thr;

    // pass 2: collect nonzero entries of attn*(1[>=kth] + 1[local])
    __shared__ int   nnz;
    __shared__ int   sidx[LISTCAP];
    __shared__ float sval[LISTCAP];
    if (tid == 0) nnz = 0;
    __syncthreads();
    int ny = n / HGd, nx = n % HGd;
    for (int m = tid; m < Ntok; m += 256) {
        float a = rowbuf[m];
        float coef = (a >= kth) ? 1.f : 0.f;
        int my = m / HGd, mx = m % HGd;
        if (abs(ny - my) + abs(nx - mx) <= 4) coef += 1.f;
        float v = a * coef;
        if (v != 0.f) {
            int pos = atomicAdd(&nnz, 1);
            if (pos < LISTCAP) { sidx[pos] = m; sval[pos] = v; }
        }
    }
    __syncthreads();
    int cnt = min(nnz, LISTCAP);

    __shared__ float smax, ssum;
    if (tid == 0) {
        float mx = -INFINITY;
        for (int e = 0; e < cnt; e++) mx = fmaxf(mx, sval[e]);
        smax = mx;
    }
    __syncthreads();
    if (tid < cnt) sval[tid] = expf(sval[tid] - smax);
    __syncthreads();
    if (tid == 0) {
        float s = 0.f;
        for (int e = 0; e < cnt; e++) s += sval[e];
        ssum = s;
    }
    __syncthreads();
    if (tid < cnt) sval[tid] = sval[tid] / ssum;
    __syncthreads();

    // sparse AV: each thread owns 8 contiguous vd dims
    const float* vbase = (f < 2) ? (v_cached + ((long)(b*2 + f)) * Ntok * VDdim)
                                 : (vout     + ((long)(b*2 + 1)) * Ntok * VDdim);
    float* orow = g_otok + ((long)(b*NFtot + f) * Ntok + n) * VDdim;
    int d0 = tid * 8;
    float acc[8] = {};
    int e = 0;
    for (; e + 2 <= cnt; e += 2) {
        float w0 = sval[e];
        float w1 = sval[e+1];
        const float* vr0 = vbase + (long)sidx[e]   * VDdim + d0;
        const float* vr1 = vbase + (long)sidx[e+1] * VDdim + d0;
        float4 a0 = *(const float4*)vr0;
        float4 a1 = *(const float4*)(vr0 + 4);
        float4 c0 = *(const float4*)vr1;
        float4 c1 = *(const float4*)(vr1 + 4);
        acc[0] += w0*a0.x + w1*c0.x; acc[1] += w0*a0.y + w1*c0.y;
        acc[2] += w0*a0.z + w1*c0.z; acc[3] += w0*a0.w + w1*c0.w;
        acc[4] += w0*a1.x + w1*c1.x; acc[5] += w0*a1.y + w1*c1.y;
        acc[6] += w0*a1.z + w1*c1.z; acc[7] += w0*a1.w + w1*c1.w;
    }
    for (; e < cnt; e++) {
        float w = sval[e];
        const float* vr = vbase + (long)sidx[e] * VDdim + d0;
        float4 v0 = *(const float4*)vr;
        float4 v1 = *(const float4*)(vr + 4);
        acc[0] += w*v0.x; acc[1] += w*v0.y; acc[2] += w*v0.z; acc[3] += w*v0.w;
        acc[4] += w*v1.x; acc[5] += w*v1.y; acc[6] += w*v1.z; acc[7] += w*v1.w;
    }
    float4 o0 = {acc[0],acc[1],acc[2],acc[3]};
    float4 o1 = {acc[4],acc[5],acc[6],acc[7]};
    *reinterpret_cast<float4*>(orow + d0)     = o0;
    *reinterpret_cast<float4*>(orow + d0 + 4) = o1;
}

// ---------------------------------- launch -----------------------------------
extern "C" void kernel_launch(void* const* d_in, const int* in_sizes, int n_in,
                              void* d_out, int out_size)
{
    (void)in_sizes; (void)n_in; (void)out_size;
    const float* x         = (const float*)d_in[0];
    const float* k_cached  = (const float*)d_in[1];
    const float* v_cached  = (const float*)d_in[2];
    const float* temperature = (const float*)d_in[3];
    const float* qk_w  = (const float*)d_in[4],  *qk_b  = (const float*)d_in[5];
    const float* qk_dw_w = (const float*)d_in[6], *qk_dw_b = (const float*)d_in[7];
    const float* v_w   = (const float*)d_in[8],  *v_b   = (const float*)d_in[9];
    const float* v_dw_w = (const float*)d_in[10], *v_dw_b = (const float*)d_in[11];
    const float* k2_w  = (const float*)d_in[12], *k2_b  = (const float*)d_in[13];
    const float* k2_dw_w = (const float*)d_in[14], *k2_dw_b = (const float*)d_in[15];
    const float* q2_w  = (const float*)d_in[16], *q2_b  = (const float*)d_in[17];
    const float* q2_dw_w = (const float*)d_in[18], *q2_dw_b = (const float*)d_in[19];
    const float* proj_w = (const float*)d_in[20], *proj_b = (const float*)d_in[21];

    float* out = (float*)d_out;
    const long OUT_K = (long)BATCH * NFtot * 128 * HW2;
    const long OUT_V = OUT_K + (long)BATCH * 2 * Ntok * D2;
    float* kout = out + OUT_K;
    float* vout = out + OUT_V;

    dim3 blk(256);

    gemm_stageA<<<dim3(288,3,BATCH), blk>>>(x, qk_w, qk_b, v_w, v_b);
    dw3x3<<<(BATCH*384*HW2 + 255)/256, blk>>>(qk_dw_w, qk_dw_b, v_dw_w, v_dw_b);
    gemm_stageC<<<dim3(288,4,BATCH), blk>>>(q2_w, q2_b, k2_w, k2_b);
    dw4x4<<<(BATCH*512*Ntok + 255)/256, blk>>>(q2_dw_w, q2_dw_b, k2_dw_w, k2_dw_b);
    norm_qk<<<dim3(Ntok, BATCH), blk>>>(kout, temperature);
    build_vnew<<<(BATCH*Ntok*VDdim + 255)/256, blk>>>(vout);
    for (int b = 0; b < BATCH; b++) {
        cudaMemcpyAsync(kout + (long)(b*2)*Ntok*D2,
                        k_cached + (long)(b*2+1)*Ntok*D2,
                        (size_t)Ntok*D2*sizeof(float), cudaMemcpyDeviceToDevice, 0);
        cudaMemcpyAsync(vout + (long)(b*2)*Ntok*VDdim,
                        v_cached + (long)(b*2+1)*Ntok*VDdim,
                        (size_t)Ntok*VDdim*sizeof(float), cudaMemcpyDeviceToDevice, 0);
    }
    attn_gemm2<<<dim3(18,18,BATCH*NFtot), blk>>>(k_cached, kout);
    sparse_attn_av<<<dim3(Ntok, NFtot, BATCH), blk>>>(v_cached, vout);
    proj_gemm2<<<dim3(288,1,BATCH*NFtot), blk>>>(proj_w, proj_b, out);
}

// round 8
// speedup vs baseline: 1.3512x; 1.0811x over previous
#include <cuda_runtime.h>
#include <math.h>

#define BATCH 2
#define HWd   192
#define HW2   (HWd*HWd)      // 36864
#define HGd   48
#define Ntok  (HGd*HGd)      // 2304
#define D2    256
#define VDdim 2048
#define NFtot 3
#define LISTCAP 128
#define MAXU   256

typedef unsigned long long u64;

// ---------------- scratch (device globals; no allocs allowed) ----------------
__device__ float g_buf1[(size_t)BATCH*384*HW2];
__device__ float g_buf2[(size_t)BATCH*384*HW2];
__device__ float g_buf3[(size_t)BATCH*512*HW2];
__device__ float g_buf4[(size_t)BATCH*512*Ntok];
__device__ float g_qtok[(size_t)BATCH*Ntok*D2];
__device__ float g_attn[(size_t)BATCH*NFtot*Ntok*Ntok];
__device__ float g_otok[(size_t)BATCH*NFtot*Ntok*VDdim];

// ---------------- packed fp32x2 primitives (Blackwell FFMA2) -----------------
__device__ __forceinline__ u64 dup2(float x) {
    u64 r;
    asm("mov.b64 %0, {%1, %1};" : "=l"(r) : "r"(__float_as_uint(x)));
    return r;
}
__device__ __forceinline__ void fma2(u64 &d, u64 a, u64 b) {
    asm("fma.rn.f32x2 %0, %1, %2, %3;" : "=l"(d) : "l"(a), "l"(b), "l"(d));
}
__device__ __forceinline__ float2 unpk(u64 v) {
    float lo, hi;
    asm("mov.b64 {%0, %1}, %2;" : "=f"(lo), "=f"(hi) : "l"(v));
    return make_float2(lo, hi);
}

// one k-step of the 8x8 fragment: 32 fma.f32x2
__device__ __forceinline__ void fma_step(
    const float* __restrict__ As_k, const float* __restrict__ Bs_k,
    int tx, int ty, u64 acc[8][4])
{
    float4 av0 = *(const float4*)(As_k + ty*4);
    float4 av1 = *(const float4*)(As_k + 64 + ty*4);
    ulonglong2 bv0 = *(const ulonglong2*)(Bs_k + tx*4);
    ulonglong2 bv1 = *(const ulonglong2*)(Bs_k + 64 + tx*4);
    u64 aa[8] = {dup2(av0.x), dup2(av0.y), dup2(av0.z), dup2(av0.w),
                 dup2(av1.x), dup2(av1.y), dup2(av1.z), dup2(av1.w)};
    u64 bb[4] = {bv0.x, bv0.y, bv1.x, bv1.y};
    #pragma unroll
    for (int i = 0; i < 8; i++) {
        fma2(acc[i][0], aa[i], bb[0]);
        fma2(acc[i][1], aa[i], bb[1]);
        fma2(acc[i][2], aa[i], bb[2]);
        fma2(acc[i][3], aa[i], bb[3]);
    }
}

// =============================================================================
// double-buffered conv GEMM body
// =============================================================================
__device__ __forceinline__ void gemm_db_conv2(
    const float* __restrict__ A, const float* __restrict__ Bbase, int K,
    float (* __restrict__ As)[16][132], float (* __restrict__ Bs)[16][128],
    int t, u64 acc[8][4])
{
    int arow = t >> 1, akq = (t & 1) * 8;
    int bk = t >> 4, bn = (t & 15) * 4;
    int tx = t & 15, ty = t >> 4;
    const float* Ap = A + (long)arow * K + akq;

    float4 a0 = *(const float4*)(Ap);
    float4 a1 = *(const float4*)(Ap + 4);
    const float* bs0 = Bbase + (long)bk * HW2;
    float4 b0 = *(const float4*)(bs0 + bn);
    float4 b1 = *(const float4*)(bs0 + bn + 64);
    As[0][akq+0][arow]=a0.x; As[0][akq+1][arow]=a0.y; As[0][akq+2][arow]=a0.z; As[0][akq+3][arow]=a0.w;
    As[0][akq+4][arow]=a1.x; As[0][akq+5][arow]=a1.y; As[0][akq+6][arow]=a1.z; As[0][akq+7][arow]=a1.w;
    *(float4*)&Bs[0][bk][bn]    = b0;
    *(float4*)&Bs[0][bk][bn+64] = b1;
    __syncthreads();
    int buf = 0;
    for (int k0 = 16; k0 <= K; k0 += 16) {
        if (k0 < K) {
            a0 = *(const float4*)(Ap + k0);
            a1 = *(const float4*)(Ap + k0 + 4);
            const float* bs2 = Bbase + (long)(k0 + bk) * HW2;
            b0 = *(const float4*)(bs2 + bn);
            b1 = *(const float4*)(bs2 + bn + 64);
        }
        #pragma unroll
        for (int kk = 0; kk < 16; kk++)
            fma_step(&As[buf][kk][0], &Bs[buf][kk][0], tx, ty, acc);
        if (k0 < K) {
            int nb = buf ^ 1;
            As[nb][akq+0][arow]=a0.x; As[nb][akq+1][arow]=a0.y; As[nb][akq+2][arow]=a0.z; As[nb][akq+3][arow]=a0.w;
            As[nb][akq+4][arow]=a1.x; As[nb][akq+5][arow]=a1.y; As[nb][akq+6][arow]=a1.z; As[nb][akq+7][arow]=a1.w;
            *(float4*)&Bs[nb][bk][bn]    = b0;
            *(float4*)&Bs[nb][bk][bn+64] = b1;
            __syncthreads();
            buf = nb;
        }
    }
}

// =============================================================================
// double-buffered TT GEMM body
// =============================================================================
__device__ __forceinline__ void gemm_db_tt2(
    const float* __restrict__ Abase, const float* __restrict__ Bbase, int K,
    float (* __restrict__ As)[16][132], float (* __restrict__ Bs)[16][132],
    int t, u64 acc[8][4])
{
    int row = t >> 1, kq = (t & 1) * 8;
    int tx = t & 15, ty = t >> 4;
    const float* Ap = Abase + (long)row * K + kq;
    const float* Bp = Bbase + (long)row * K + kq;

    float4 a0 = *(const float4*)(Ap);
    float4 a1 = *(const float4*)(Ap + 4);
    float4 b0 = *(const float4*)(Bp);
    float4 b1 = *(const float4*)(Bp + 4);
    As[0][kq+0][row]=a0.x; As[0][kq+1][row]=a0.y; As[0][kq+2][row]=a0.z; As[0][kq+3][row]=a0.w;
    As[0][kq+4][row]=a1.x; As[0][kq+5][row]=a1.y; As[0][kq+6][row]=a1.z; As[0][kq+7][row]=a1.w;
    Bs[0][kq+0][row]=b0.x; Bs[0][kq+1][row]=b0.y; Bs[0][kq+2][row]=b0.z; Bs[0][kq+3][row]=b0.w;
    Bs[0][kq+4][row]=b1.x; Bs[0][kq+5][row]=b1.y; Bs[0][kq+6][row]=b1.z; Bs[0][kq+7][row]=b1.w;
    __syncthreads();
    int buf = 0;
    for (int k0 = 16; k0 <= K; k0 += 16) {
        if (k0 < K) {
            a0 = *(const float4*)(Ap + k0);
            a1 = *(const float4*)(Ap + k0 + 4);
            b0 = *(const float4*)(Bp + k0);
            b1 = *(const float4*)(Bp + k0 + 4);
        }
        #pragma unroll
        for (int kk = 0; kk < 16; kk++)
            fma_step(&As[buf][kk][0], &Bs[buf][kk][0], tx, ty, acc);
        if (k0 < K) {
            int nb = buf ^ 1;
            As[nb][kq+0][row]=a0.x; As[nb][kq+1][row]=a0.y; As[nb][kq+2][row]=a0.z; As[nb][kq+3][row]=a0.w;
            As[nb][kq+4][row]=a1.x; As[nb][kq+5][row]=a1.y; As[nb][kq+6][row]=a1.z; As[nb][kq+7][row]=a1.w;
            Bs[nb][kq+0][row]=b0.x; Bs[nb][kq+1][row]=b0.y; Bs[nb][kq+2][row]=b0.z; Bs[nb][kq+3][row]=b0.w;
            Bs[nb][kq+4][row]=b1.x; Bs[nb][kq+5][row]=b1.y; Bs[nb][kq+6][row]=b1.z; Bs[nb][kq+7][row]=b1.w;
            __syncthreads();
            buf = nb;
        }
    }
}

__device__ __forceinline__ void gemm128_store2(
    float* __restrict__ Crow, const float* __restrict__ bias,
    int t, u64 acc[8][4], long ldc)
{
    int tx = t & 15, ty = t >> 4;
    #pragma unroll
    for (int i = 0; i < 8; i++) {
        int m = (i < 4) ? (ty*4 + i) : (64 + ty*4 + i - 4);
        float bv = bias ? bias[m] : 0.f;
        float2 p0 = unpk(acc[i][0]), p1 = unpk(acc[i][1]);
        float2 p2 = unpk(acc[i][2]), p3 = unpk(acc[i][3]);
        float4 o0 = {p0.x+bv, p0.y+bv, p1.x+bv, p1.y+bv};
        float4 o1 = {p2.x+bv, p2.y+bv, p3.x+bv, p3.y+bv};
        *(float4*)&Crow[(long)m*ldc + tx*4]      = o0;
        *(float4*)&Crow[(long)m*ldc + 64 + tx*4] = o1;
    }
}

// stage A
__global__ void __launch_bounds__(256,2) gemm_stageA(
    const float* __restrict__ x,
    const float* __restrict__ qk_w, const float* __restrict__ qk_b,
    const float* __restrict__ v_w,  const float* __restrict__ v_b)
{
    int n0 = blockIdx.x * 128, y = blockIdx.y, b = blockIdx.z;
    int t = threadIdx.x;
    __shared__ float As[2][16][132];
    __shared__ float Bs[2][16][128];
    u64 acc[8][4] = {};
    const float* A   = (y < 2) ? (qk_w + (long)y*128*128) : v_w;
    const float* bia = (y < 2) ? (qk_b + y*128)           : v_b;
    int cch          = (y < 2) ? (y*128)                  : 256;
    gemm_db_conv2(A, x + (long)b*128*HW2 + n0, 128, As, Bs, t, acc);
    gemm128_store2(g_buf1 + ((long)b*384 + cch) * HW2 + n0, bia, t, acc, HW2);
}

// stage C
__global__ void __launch_bounds__(256,2) gemm_stageC(
    const float* __restrict__ q2_w, const float* __restrict__ q2_b,
    const float* __restrict__ k2_w, const float* __restrict__ k2_b)
{
    int n0 = blockIdx.x * 128, y = blockIdx.y, b = blockIdx.z;
    int t = threadIdx.x;
    __shared__ float As[2][16][132];
    __shared__ float Bs[2][16][128];
    u64 acc[8][4] = {};
    const float* A   = (y < 2) ? (q2_w + (long)y*128*128) : (k2_w + (long)(y-2)*128*128);
    const float* bia = (y < 2) ? (q2_b + y*128)           : (k2_b + (y-2)*128);
    const float* Bbase = g_buf2 + ((long)b*384 + ((y < 2) ? 0 : 128)) * HW2 + n0;
    gemm_db_conv2(A, Bbase, 128, As, Bs, t, acc);
    gemm128_store2(g_buf3 + ((long)b*512 + y*128) * HW2 + n0, bia, t, acc, HW2);
}

// attention GEMM
__global__ void __launch_bounds__(256,2) attn_gemm2(
    const float* __restrict__ kc, const float* __restrict__ knew)
{
    int z = blockIdx.z; int b = z / NFtot, f = z % NFtot;
    const float* Qp = g_qtok + (long)b * Ntok * D2;
    const float* Kp = (f < 2) ? (kc   + ((long)(b*2 + f)) * Ntok * D2)
                              : (knew + ((long)(b*2 + 1)) * Ntok * D2);
    int m0 = blockIdx.y * 128, n0 = blockIdx.x * 128;
    int t = threadIdx.x;
    int tx = t & 15, ty = t >> 4;
    __shared__ float As[2][16][132];
    __shared__ float Bs[2][16][132];
    u64 acc[8][4] = {};
    gemm_db_tt2(Qp + (long)m0 * D2, Kp + (long)n0 * D2, D2, As, Bs, t, acc);
    float* Cp = g_attn + (long)z * Ntok * Ntok;
    #pragma unroll
    for (int i = 0; i < 8; i++) {
        int m = (i < 4) ? (ty*4 + i) : (64 + ty*4 + i - 4);
        float2 p0 = unpk(acc[i][0]), p1 = unpk(acc[i][1]);
        float2 p2 = unpk(acc[i][2]), p3 = unpk(acc[i][3]);
        float4 o0 = {p0.x, p0.y, p1.x, p1.y};
        float4 o1 = {p2.x, p2.y, p3.x, p3.y};
        *(float4*)&Cp[(long)(m0+m)*Ntok + n0 + tx*4]      = o0;
        *(float4*)&Cp[(long)(m0+m)*Ntok + n0 + 64 + tx*4] = o1;
    }
}

// proj 1x1 GEMM with fused window de-permute gather
__global__ void __launch_bounds__(256,2) proj_gemm2(
    const float* __restrict__ W, const float* __restrict__ bias,
    float* __restrict__ Out)
{
    int z  = blockIdx.z;
    int n0 = blockIdx.x * 128;
    int t = threadIdx.x;
    int tx = t & 15, ty = t >> 4;
    __shared__ float As[2][16][132];
    __shared__ float Bs[2][16][132];
    u64 acc[8][4] = {};
    int row = t >> 1;
    int p = n0 + row;
    int h = p / HWd, w = p % HWd;
    int token = (h % HGd) * HGd + (w % HGd);
    int vbase = ((h / HGd) * 4 + (w / HGd)) * 128;
    {
        int kq = (t & 1) * 8;
        const float* Ap = W + (long)row * 128 + kq;
        const float* Bp = g_otok + ((long)z * Ntok + token) * VDdim + vbase + kq;
        float4 a0 = *(const float4*)(Ap);
        float4 a1 = *(const float4*)(Ap + 4);
        float4 b0 = *(const float4*)(Bp);
        float4 b1 = *(const float4*)(Bp + 4);
        As[0][kq+0][row]=a0.x; As[0][kq+1][row]=a0.y; As[0][kq+2][row]=a0.z; As[0][kq+3][row]=a0.w;
        As[0][kq+4][row]=a1.x; As[0][kq+5][row]=a1.y; As[0][kq+6][row]=a1.z; As[0][kq+7][row]=a1.w;
        Bs[0][kq+0][row]=b0.x; Bs[0][kq+1][row]=b0.y; Bs[0][kq+2][row]=b0.z; Bs[0][kq+3][row]=b0.w;
        Bs[0][kq+4][row]=b1.x; Bs[0][kq+5][row]=b1.y; Bs[0][kq+6][row]=b1.z; Bs[0][kq+7][row]=b1.w;
        __syncthreads();
        int buf = 0;
        for (int k0 = 16; k0 <= 128; k0 += 16) {
            if (k0 < 128) {
                a0 = *(const float4*)(Ap + k0);
                a1 = *(const float4*)(Ap + k0 + 4);
                b0 = *(const float4*)(Bp + k0);
                b1 = *(const float4*)(Bp + k0 + 4);
            }
            #pragma unroll
            for (int kk = 0; kk < 16; kk++)
                fma_step(&As[buf][kk][0], &Bs[buf][kk][0], tx, ty, acc);
            if (k0 < 128) {
                int nb = buf ^ 1;
                As[nb][kq+0][row]=a0.x; As[nb][kq+1][row]=a0.y; As[nb][kq+2][row]=a0.z; As[nb][kq+3][row]=a0.w;
                As[nb][kq+4][row]=a1.x; As[nb][kq+5][row]=a1.y; As[nb][kq+6][row]=a1.z; As[nb][kq+7][row]=a1.w;
                Bs[nb][kq+0][row]=b0.x; Bs[nb][kq+1][row]=b0.y; Bs[nb][kq+2][row]=b0.z; Bs[nb][kq+3][row]=b0.w;
                Bs[nb][kq+4][row]=b1.x; Bs[nb][kq+5][row]=b1.y; Bs[nb][kq+6][row]=b1.z; Bs[nb][kq+7][row]=b1.w;
                __syncthreads();
                buf = nb;
            }
        }
    }
    #pragma unroll
    for (int i = 0; i < 8; i++) {
        int m = (i < 4) ? (ty*4 + i) : (64 + ty*4 + i - 4);
        float bv = bias[m];
        float2 p0 = unpk(acc[i][0]), p1 = unpk(acc[i][1]);
        float2 p2 = unpk(acc[i][2]), p3 = unpk(acc[i][3]);
        float4 o0 = {p0.x+bv, p0.y+bv, p1.x+bv, p1.y+bv};
        float4 o1 = {p2.x+bv, p2.y+bv, p3.x+bv, p3.y+bv};
        *(float4*)&Out[((long)z*128 + m)*HW2 + n0 + tx*4]      = o0;
        *(float4*)&Out[((long)z*128 + m)*HW2 + n0 + 64 + tx*4] = o1;
    }
}

// ---------------- depthwise 3x3 pad1 ------------------------------------------
__global__ void dw3x3(const float* __restrict__ qk_dw_w, const float* __restrict__ qk_dw_b,
                      const float* __restrict__ v_dw_w,  const float* __restrict__ v_dw_b)
{
    int idx = blockIdx.x * 256 + threadIdx.x;
    if (idx >= BATCH*384*HW2) return;
    int p  = idx % HW2;
    int ch = (idx / HW2) % 384;
    int b  = idx / (384*HW2);
    int h = p / HWd, w = p % HWd;
    const float* wgt; float bv;
    if (ch < 256) { wgt = qk_dw_w + ch*9;        bv = qk_dw_b[ch]; }
    else          { wgt = v_dw_w  + (ch-256)*9;  bv = v_dw_b[ch-256]; }
    const float* in = g_buf1 + ((long)(b*384 + ch)) * HW2;
    float s = bv;
    #pragma unroll
    for (int ky = 0; ky < 3; ky++) {
        int y = h + ky - 1;
        if ((unsigned)y >= (unsigned)HWd) continue;
        #pragma unroll
        for (int kx = 0; kx < 3; kx++) {
            int x = w + kx - 1;
            if ((unsigned)x >= (unsigned)HWd) continue;
            s += wgt[ky*3+kx] * in[y*HWd + x];
        }
    }
    g_buf2[idx] = s;
}

// ---------------- depthwise 4x4 stride4 pad1 ----------------------------------
__global__ void dw4x4(const float* __restrict__ q2_dw_w, const float* __restrict__ q2_dw_b,
                      const float* __restrict__ k2_dw_w, const float* __restrict__ k2_dw_b)
{
    int idx = blockIdx.x * 256 + threadIdx.x;
    if (idx >= BATCH*512*Ntok) return;
    int t  = idx % Ntok;
    int ch = (idx / Ntok) % 512;
    int b  = idx / (512*Ntok);
    int oy = t / HGd, ox = t % HGd;
    const float* wgt; float bv;
    if (ch < 256) { wgt = q2_dw_w + ch*16;       bv = q2_dw_b[ch]; }
    else          { wgt = k2_dw_w + (ch-256)*16; bv = k2_dw_b[ch-256]; }
    const float* in = g_buf3 + ((long)(b*512 + ch)) * HW2;
    float s = bv;
    #pragma unroll
    for (int ky = 0; ky < 4; ky++) {
        int y = oy*4 - 1 + ky;
        if ((unsigned)y >= (unsigned)HWd) continue;
        #pragma unroll
        for (int kx = 0; kx < 4; kx++) {
            int x = ox*4 - 1 + kx;
            if ((unsigned)x >= (unsigned)HWd) continue;
            s += wgt[ky*4+kx] * in[y*HWd + x];
        }
    }
    g_buf4[idx] = s;
}

// ---------------- l2 normalize + token-major q/k ------------------------------
__global__ void __launch_bounds__(256) norm_qk(float* __restrict__ kout,
                                               const float* __restrict__ temp)
{
    int token = blockIdx.x, b = blockIdx.y, d = threadIdx.x;
    float qv = g_buf4[((long)b*512 + d)       * Ntok + token];
    float kv = g_buf4[((long)b*512 + 256 + d) * Ntok + token];
    __shared__ float red[256];
    __shared__ float qinv_s, kinv_s;
    red[d] = qv*qv; __syncthreads();
    for (int s = 128; s > 0; s >>= 1) { if (d < s) red[d] += red[d+s]; __syncthreads(); }
    if (d == 0) qinv_s = (*temp) / fmaxf(sqrtf(red[0]), 1e-12f);
    __syncthreads();
    red[d] = kv*kv; __syncthreads();
    for (int s = 128; s > 0; s >>= 1) { if (d < s) red[d] += red[d+s]; __syncthreads(); }
    if (d == 0) kinv_s = 1.f / fmaxf(sqrtf(red[0]), 1e-12f);
    __syncthreads();
    g_qtok[((long)b*Ntok + token) * D2 + d] = qv * qinv_s;
    kout  [((long)(b*2 + 1)*Ntok + token) * D2 + d] = kv * kinv_s;
}

// ---------------- build v_new -------------------------------------------------
__global__ void build_vnew(float* __restrict__ vout)
{
    int idx = blockIdx.x * 256 + threadIdx.x;
    if (idx >= BATCH*Ntok*VDdim) return;
    int vd    = idx % VDdim;
    int token = (idx / VDdim) % Ntok;
    int b     = idx / (Ntok*VDdim);
    int c  = vd & 127;
    int p2 = (vd >> 7) & 3;
    int p1 = vd >> 9;
    int hi = token / HGd, wi = token % HGd;
    float val = g_buf2[((long)(b*384 + 256 + c)) * HW2 + (p1*HGd + hi) * HWd + (p2*HGd + wi)];
    vout[((long)(b*2 + 1)*Ntok + token) * VDdim + vd] = val;
}

// =============================================================================
// sparse_attn_av4: one block = 2x2 query tile. Per-query select (identical math
// to the passing single-query kernel), then a UNION gather list with a rank-
// indexed weight table so each v-row chunk is loaded once and FMA'd into 4
// accumulator sets (register-level reuse; no smem staging).
// grid: (576 tiles, 6 zf), block 256
// =============================================================================
__global__ void __launch_bounds__(256) sparse_attn_av4(
    const float* __restrict__ v_cached, const float* __restrict__ vout)
{
    int tile = blockIdx.x;               // 0..575
    int z    = blockIdx.y;               // b*3+f
    int b = z / NFtot, f = z % NFtot;
    int qy0 = (tile / 24) * 2, qx0 = (tile % 24) * 2;
    int tid = threadIdx.x;

    __shared__ float rowbuf[Ntok];
    __shared__ float cand[256*5];
    __shared__ float red[256];
    __shared__ int   sidx[4][LISTCAP];
    __shared__ float sval[4][LISTCAP];
    __shared__ int   scnt[4];
    __shared__ unsigned umask[72];
    __shared__ int   ubase[73];
    __shared__ int   nnz;
    __shared__ float smax, ssum;
    __shared__ int   uidx[MAXU];
    __shared__ float Wt[4][MAXU];

    if (tid < 72) umask[tid] = 0;

    for (int q = 0; q < 4; q++) {
        int ny = qy0 + (q >> 1), nx = qx0 + (q & 1);
        int n = ny * HGd + nx;
        const float* arow = g_attn + ((long)z * Ntok + n) * Ntok;
        __syncthreads();
        for (int m = tid*4; m < Ntok; m += 1024)
            *(float4*)&rowbuf[m] = *(const float4*)&arow[m];
        if (tid == 0) nnz = 0;
        __syncthreads();

        // per-thread top-5
        float t5[5] = {-INFINITY,-INFINITY,-INFINITY,-INFINITY,-INFINITY};
        for (int m = tid; m < Ntok; m += 256) {
            float v = rowbuf[m];
            if (v > t5[4]) {
                t5[4] = v;
                #pragma unroll
                for (int i = 4; i > 0; i--)
                    if (t5[i] > t5[i-1]) { float tmp = t5[i-1]; t5[i-1] = t5[i]; t5[i] = tmp; }
            }
        }
        #pragma unroll
        for (int i = 0; i < 5; i++) cand[tid*5 + i] = t5[i];
        __syncthreads();

        float thr = INFINITY;
        for (int r = 0; r < 5; r++) {
            float lm = -INFINITY;
            #pragma unroll
            for (int i = 0; i < 5; i++) {
                float v = cand[tid*5 + i];
                if (v < thr && v > lm) lm = v;
            }
            red[tid] = lm; __syncthreads();
            for (int s = 128; s > 0; s >>= 1) { if (tid < s) red[tid] = fmaxf(red[tid], red[tid+s]); __syncthreads(); }
            thr = red[0];
            __syncthreads();
        }
        float kth = thr;

        // collect nonzero entries; OR into union bitmap
        for (int m = tid; m < Ntok; m += 256) {
            float a = rowbuf[m];
            float coef = (a >= kth) ? 1.f : 0.f;
            int my = m / HGd, mx = m % HGd;
            if (abs(ny - my) + abs(nx - mx) <= 4) coef += 1.f;
            float v = a * coef;
            if (v != 0.f) {
                int pos = atomicAdd(&nnz, 1);
                if (pos < LISTCAP) { sidx[q][pos] = m; sval[q][pos] = v; }
                atomicOr(&umask[m >> 5], 1u << (m & 31));
            }
        }
        __syncthreads();
        int cnt = min(nnz, LISTCAP);

        if (tid == 0) {
            float mx = -INFINITY;
            for (int e = 0; e < cnt; e++) mx = fmaxf(mx, sval[q][e]);
            smax = mx;
        }
        __syncthreads();
        if (tid < cnt) sval[q][tid] = expf(sval[q][tid] - smax);
        __syncthreads();
        if (tid == 0) {
            float s = 0.f;
            for (int e = 0; e < cnt; e++) s += sval[q][e];
            ssum = s;
            scnt[q] = cnt;
        }
        __syncthreads();
        if (tid < cnt) sval[q][tid] = sval[q][tid] / ssum;
    }
    __syncthreads();

    // union prefix ranks
    if (tid == 0) {
        int s = 0;
        for (int w = 0; w < 72; w++) { ubase[w] = s; s += __popc(umask[w]); }
        ubase[72] = s;
    }
    __syncthreads();
    int U = min(ubase[72], MAXU);

    // zero weight table, build union index list
    for (int i = tid; i < 4*MAXU; i += 256) ((float*)Wt)[i] = 0.f;
    __syncthreads();
    if (tid < 72) {
        unsigned bits = umask[tid];
        int pos = ubase[tid];
        while (bits) {
            int bit = __ffs(bits) - 1; bits &= bits - 1;
            if (pos < MAXU) uidx[pos] = tid*32 + bit;
            pos++;
        }
    }
    __syncthreads();
    // scatter per-query weights by union rank
    for (int i = tid; i < 4*LISTCAP; i += 256) {
        int q = i >> 7, e = i & (LISTCAP-1);
        if (e < scnt[q]) {
            int m = sidx[q][e];
            int w32 = m >> 5, bit = m & 31;
            int rank = ubase[w32] + __popc(umask[w32] & ((1u << bit) - 1u));
            if (rank < MAXU) Wt[q][rank] = sval[q][e];
        }
    }
    __syncthreads();

    // AV over union list: one load, 4 accumulator sets
    const float* vbase = (f < 2) ? (v_cached + ((long)(b*2 + f)) * Ntok * VDdim)
                                 : (vout     + ((long)(b*2 + 1)) * Ntok * VDdim);
    int d0 = tid * 8;
    float a0_[8] = {}, a1_[8] = {}, a2_[8] = {}, a3_[8] = {};
    for (int e = 0; e < U; e++) {
        int m = uidx[e];
        const float* vr = vbase + (long)m * VDdim + d0;
        float4 v0 = *(const float4*)vr;
        float4 v1 = *(const float4*)(vr + 4);
        float w0 = Wt[0][e], w1 = Wt[1][e], w2 = Wt[2][e], w3 = Wt[3][e];
        a0_[0]+=w0*v0.x; a0_[1]+=w0*v0.y; a0_[2]+=w0*v0.z; a0_[3]+=w0*v0.w;
        a0_[4]+=w0*v1.x; a0_[5]+=w0*v1.y; a0_[6]+=w0*v1.z; a0_[7]+=w0*v1.w;
        a1_[0]+=w1*v0.x; a1_[1]+=w1*v0.y; a1_[2]+=w1*v0.z; a1_[3]+=w1*v0.w;
        a1_[4]+=w1*v1.x; a1_[5]+=w1*v1.y; a1_[6]+=w1*v1.z; a1_[7]+=w1*v1.w;
        a2_[0]+=w2*v0.x; a2_[1]+=w2*v0.y; a2_[2]+=w2*v0.z; a2_[3]+=w2*v0.w;
        a2_[4]+=w2*v1.x; a2_[5]+=w2*v1.y; a2_[6]+=w2*v1.z; a2_[7]+=w2*v1.w;
        a3_[0]+=w3*v0.x; a3_[1]+=w3*v0.y; a3_[2]+=w3*v0.z; a3_[3]+=w3*v0.w;
        a3_[4]+=w3*v1.x; a3_[5]+=w3*v1.y; a3_[6]+=w3*v1.z; a3_[7]+=w3*v1.w;
    }
    #pragma unroll
    for (int q = 0; q < 4; q++) {
        const float* acc = (q == 0) ? a0_ : (q == 1) ? a1_ : (q == 2) ? a2_ : a3_;
        int ny = qy0 + (q >> 1), nx = qx0 + (q & 1);
        float* orow = g_otok + ((long)z * Ntok + ny*HGd + nx) * VDdim + d0;
        *(float4*)orow       = make_float4(acc[0], acc[1], acc[2], acc[3]);
        *(float4*)(orow + 4) = make_float4(acc[4], acc[5], acc[6], acc[7]);
    }
}

// ---------------------------------- launch -----------------------------------
extern "C" void kernel_launch(void* const* d_in, const int* in_sizes, int n_in,
                              void* d_out, int out_size)
{
    (void)in_sizes; (void)n_in; (void)out_size;
    const float* x         = (const float*)d_in[0];
    const float* k_cached  = (const float*)d_in[1];
    const float* v_cached  = (const float*)d_in[2];
    const float* temperature = (const float*)d_in[3];
    const float* qk_w  = (const float*)d_in[4],  *qk_b  = (const float*)d_in[5];
    const float* qk_dw_w = (const float*)d_in[6], *qk_dw_b = (const float*)d_in[7];
    const float* v_w   = (const float*)d_in[8],  *v_b   = (const float*)d_in[9];
    const float* v_dw_w = (const float*)d_in[10], *v_dw_b = (const float*)d_in[11];
    const float* k2_w  = (const float*)d_in[12], *k2_b  = (const float*)d_in[13];
    const float* k2_dw_w = (const float*)d_in[14], *k2_dw_b = (const float*)d_in[15];
    const float* q2_w  = (const float*)d_in[16], *q2_b  = (const float*)d_in[17];
    const float* q2_dw_w = (const float*)d_in[18], *q2_dw_b = (const float*)d_in[19];
    const float* proj_w = (const float*)d_in[20], *proj_b = (const float*)d_in[21];

    float* out = (float*)d_out;
    const long OUT_K = (long)BATCH * NFtot * 128 * HW2;
    const long OUT_V = OUT_K + (long)BATCH * 2 * Ntok * D2;
    float* kout = out + OUT_K;
    float* vout = out + OUT_V;

    dim3 blk(256);

    gemm_stageA<<<dim3(288,3,BATCH), blk>>>(x, qk_w, qk_b, v_w, v_b);
    dw3x3<<<(BATCH*384*HW2 + 255)/256, blk>>>(qk_dw_w, qk_dw_b, v_dw_w, v_dw_b);
    gemm_stageC<<<dim3(288,4,BATCH), blk>>>(q2_w, q2_b, k2_w, k2_b);
    dw4x4<<<(BATCH*512*Ntok + 255)/256, blk>>>(q2_dw_w, q2_dw_b, k2_dw_w, k2_dw_b);
    norm_qk<<<dim3(Ntok, BATCH), blk>>>(kout, temperature);
    build_vnew<<<(BATCH*Ntok*VDdim + 255)/256, blk>>>(vout);
    for (int b = 0; b < BATCH; b++) {
        cudaMemcpyAsync(kout + (long)(b*2)*Ntok*D2,
                        k_cached + (long)(b*2+1)*Ntok*D2,
                        (size_t)Ntok*D2*sizeof(float), cudaMemcpyDeviceToDevice, 0);
        cudaMemcpyAsync(vout + (long)(b*2)*Ntok*VDdim,
                        v_cached + (long)(b*2+1)*Ntok*VDdim,
                        (size_t)Ntok*VDdim*sizeof(float), cudaMemcpyDeviceToDevice, 0);
    }
    attn_gemm2<<<dim3(18,18,BATCH*NFtot), blk>>>(k_cached, kout);
    sparse_attn_av4<<<dim3(576, BATCH*NFtot), blk>>>(v_cached, vout);
    proj_gemm2<<<dim3(288,1,BATCH*NFtot), blk>>>(proj_w, proj_b, out);
}

// round 9
// speedup vs baseline: 1.3603x; 1.0067x over previous
#include <cuda_runtime.h>
#include <math.h>

#define BATCH 2
#define HWd   192
#define HW2   (HWd*HWd)      // 36864
#define HGd   48
#define Ntok  (HGd*HGd)      // 2304
#define D2    256
#define VDdim 2048
#define NFtot 3
#define LISTCAP 128
#define MAXU   256

typedef unsigned long long u64;

// ---------------- scratch (device globals; no allocs allowed) ----------------
__device__ float g_buf1[(size_t)BATCH*384*HW2];
__device__ float g_buf2[(size_t)BATCH*384*HW2];
__device__ float g_buf3[(size_t)BATCH*512*HW2];
__device__ float g_buf4[(size_t)BATCH*512*Ntok];
__device__ float g_qtok[(size_t)BATCH*Ntok*D2];
__device__ float g_attn[(size_t)BATCH*NFtot*Ntok*Ntok];
__device__ float g_otok[(size_t)BATCH*NFtot*Ntok*VDdim];

// ---------------- packed fp32x2 primitives (Blackwell FFMA2) -----------------
__device__ __forceinline__ u64 dup2(float x) {
    u64 r;
    asm("mov.b64 %0, {%1, %1};" : "=l"(r) : "r"(__float_as_uint(x)));
    return r;
}
__device__ __forceinline__ void fma2(u64 &d, u64 a, u64 b) {
    asm("fma.rn.f32x2 %0, %1, %2, %3;" : "=l"(d) : "l"(a), "l"(b), "l"(d));
}
__device__ __forceinline__ float2 unpk(u64 v) {
    float lo, hi;
    asm("mov.b64 {%0, %1}, %2;" : "=f"(lo), "=f"(hi) : "l"(v));
    return make_float2(lo, hi);
}

// one k-step of the 8x8 fragment: 32 fma.f32x2
__device__ __forceinline__ void fma_step(
    const float* __restrict__ As_k, const float* __restrict__ Bs_k,
    int tx, int ty, u64 acc[8][4])
{
    float4 av0 = *(const float4*)(As_k + ty*4);
    float4 av1 = *(const float4*)(As_k + 64 + ty*4);
    ulonglong2 bv0 = *(const ulonglong2*)(Bs_k + tx*4);
    ulonglong2 bv1 = *(const ulonglong2*)(Bs_k + 64 + tx*4);
    u64 aa[8] = {dup2(av0.x), dup2(av0.y), dup2(av0.z), dup2(av0.w),
                 dup2(av1.x), dup2(av1.y), dup2(av1.z), dup2(av1.w)};
    u64 bb[4] = {bv0.x, bv0.y, bv1.x, bv1.y};
    #pragma unroll
    for (int i = 0; i < 8; i++) {
        fma2(acc[i][0], aa[i], bb[0]);
        fma2(acc[i][1], aa[i], bb[1]);
        fma2(acc[i][2], aa[i], bb[2]);
        fma2(acc[i][3], aa[i], bb[3]);
    }
}

// =============================================================================
// double-buffered conv GEMM body
// =============================================================================
__device__ __forceinline__ void gemm_db_conv2(
    const float* __restrict__ A, const float* __restrict__ Bbase, int K,
    float (* __restrict__ As)[16][132], float (* __restrict__ Bs)[16][128],
    int t, u64 acc[8][4])
{
    int arow = t >> 1, akq = (t & 1) * 8;
    int bk = t >> 4, bn = (t & 15) * 4;
    int tx = t & 15, ty = t >> 4;
    const float* Ap = A + (long)arow * K + akq;

    float4 a0 = *(const float4*)(Ap);
    float4 a1 = *(const float4*)(Ap + 4);
    const float* bs0 = Bbase + (long)bk * HW2;
    float4 b0 = *(const float4*)(bs0 + bn);
    float4 b1 = *(const float4*)(bs0 + bn + 64);
    As[0][akq+0][arow]=a0.x; As[0][akq+1][arow]=a0.y; As[0][akq+2][arow]=a0.z; As[0][akq+3][arow]=a0.w;
    As[0][akq+4][arow]=a1.x; As[0][akq+5][arow]=a1.y; As[0][akq+6][arow]=a1.z; As[0][akq+7][arow]=a1.w;
    *(float4*)&Bs[0][bk][bn]    = b0;
    *(float4*)&Bs[0][bk][bn+64] = b1;
    __syncthreads();
    int buf = 0;
    for (int k0 = 16; k0 <= K; k0 += 16) {
        if (k0 < K) {
            a0 = *(const float4*)(Ap + k0);
            a1 = *(const float4*)(Ap + k0 + 4);
            const float* bs2 = Bbase + (long)(k0 + bk) * HW2;
            b0 = *(const float4*)(bs2 + bn);
            b1 = *(const float4*)(bs2 + bn + 64);
        }
        #pragma unroll
        for (int kk = 0; kk < 16; kk++)
            fma_step(&As[buf][kk][0], &Bs[buf][kk][0], tx, ty, acc);
        if (k0 < K) {
            int nb = buf ^ 1;
            As[nb][akq+0][arow]=a0.x; As[nb][akq+1][arow]=a0.y; As[nb][akq+2][arow]=a0.z; As[nb][akq+3][arow]=a0.w;
            As[nb][akq+4][arow]=a1.x; As[nb][akq+5][arow]=a1.y; As[nb][akq+6][arow]=a1.z; As[nb][akq+7][arow]=a1.w;
            *(float4*)&Bs[nb][bk][bn]    = b0;
            *(float4*)&Bs[nb][bk][bn+64] = b1;
            __syncthreads();
            buf = nb;
        }
    }
}

// =============================================================================
// double-buffered TT GEMM body
// =============================================================================
__device__ __forceinline__ void gemm_db_tt2(
    const float* __restrict__ Abase, const float* __restrict__ Bbase, int K,
    float (* __restrict__ As)[16][132], float (* __restrict__ Bs)[16][132],
    int t, u64 acc[8][4])
{
    int row = t >> 1, kq = (t & 1) * 8;
    int tx = t & 15, ty = t >> 4;
    const float* Ap = Abase + (long)row * K + kq;
    const float* Bp = Bbase + (long)row * K + kq;

    float4 a0 = *(const float4*)(Ap);
    float4 a1 = *(const float4*)(Ap + 4);
    float4 b0 = *(const float4*)(Bp);
    float4 b1 = *(const float4*)(Bp + 4);
    As[0][kq+0][row]=a0.x; As[0][kq+1][row]=a0.y; As[0][kq+2][row]=a0.z; As[0][kq+3][row]=a0.w;
    As[0][kq+4][row]=a1.x; As[0][kq+5][row]=a1.y; As[0][kq+6][row]=a1.z; As[0][kq+7][row]=a1.w;
    Bs[0][kq+0][row]=b0.x; Bs[0][kq+1][row]=b0.y; Bs[0][kq+2][row]=b0.z; Bs[0][kq+3][row]=b0.w;
    Bs[0][kq+4][row]=b1.x; Bs[0][kq+5][row]=b1.y; Bs[0][kq+6][row]=b1.z; Bs[0][kq+7][row]=b1.w;
    __syncthreads();
    int buf = 0;
    for (int k0 = 16; k0 <= K; k0 += 16) {
        if (k0 < K) {
            a0 = *(const float4*)(Ap + k0);
            a1 = *(const float4*)(Ap + k0 + 4);
            b0 = *(const float4*)(Bp + k0);
            b1 = *(const float4*)(Bp + k0 + 4);
        }
        #pragma unroll
        for (int kk = 0; kk < 16; kk++)
            fma_step(&As[buf][kk][0], &Bs[buf][kk][0], tx, ty, acc);
        if (k0 < K) {
            int nb = buf ^ 1;
            As[nb][kq+0][row]=a0.x; As[nb][kq+1][row]=a0.y; As[nb][kq+2][row]=a0.z; As[nb][kq+3][row]=a0.w;
            As[nb][kq+4][row]=a1.x; As[nb][kq+5][row]=a1.y; As[nb][kq+6][row]=a1.z; As[nb][kq+7][row]=a1.w;
            Bs[nb][kq+0][row]=b0.x; Bs[nb][kq+1][row]=b0.y; Bs[nb][kq+2][row]=b0.z; Bs[nb][kq+3][row]=b0.w;
            Bs[nb][kq+4][row]=b1.x; Bs[nb][kq+5][row]=b1.y; Bs[nb][kq+6][row]=b1.z; Bs[nb][kq+7][row]=b1.w;
            __syncthreads();
            buf = nb;
        }
    }
}

__device__ __forceinline__ void gemm128_store2(
    float* __restrict__ Crow, const float* __restrict__ bias,
    int t, u64 acc[8][4], long ldc)
{
    int tx = t & 15, ty = t >> 4;
    #pragma unroll
    for (int i = 0; i < 8; i++) {
        int m = (i < 4) ? (ty*4 + i) : (64 + ty*4 + i - 4);
        float bv = bias ? bias[m] : 0.f;
        float2 p0 = unpk(acc[i][0]), p1 = unpk(acc[i][1]);
        float2 p2 = unpk(acc[i][2]), p3 = unpk(acc[i][3]);
        float4 o0 = {p0.x+bv, p0.y+bv, p1.x+bv, p1.y+bv};
        float4 o1 = {p2.x+bv, p2.y+bv, p3.x+bv, p3.y+bv};
        *(float4*)&Crow[(long)m*ldc + tx*4]      = o0;
        *(float4*)&Crow[(long)m*ldc + 64 + tx*4] = o1;
    }
}

// stage A
__global__ void __launch_bounds__(256,2) gemm_stageA(
    const float* __restrict__ x,
    const float* __restrict__ qk_w, const float* __restrict__ qk_b,
    const float* __restrict__ v_w,  const float* __restrict__ v_b)
{
    int n0 = blockIdx.x * 128, y = blockIdx.y, b = blockIdx.z;
    int t = threadIdx.x;
    __shared__ float As[2][16][132];
    __shared__ float Bs[2][16][128];
    u64 acc[8][4] = {};
    const float* A   = (y < 2) ? (qk_w + (long)y*128*128) : v_w;
    const float* bia = (y < 2) ? (qk_b + y*128)           : v_b;
    int cch          = (y < 2) ? (y*128)                  : 256;
    gemm_db_conv2(A, x + (long)b*128*HW2 + n0, 128, As, Bs, t, acc);
    gemm128_store2(g_buf1 + ((long)b*384 + cch) * HW2 + n0, bia, t, acc, HW2);
}

// stage C
__global__ void __launch_bounds__(256,2) gemm_stageC(
    const float* __restrict__ q2_w, const float* __restrict__ q2_b,
    const float* __restrict__ k2_w, const float* __restrict__ k2_b)
{
    int n0 = blockIdx.x * 128, y = blockIdx.y, b = blockIdx.z;
    int t = threadIdx.x;
    __shared__ float As[2][16][132];
    __shared__ float Bs[2][16][128];
    u64 acc[8][4] = {};
    const float* A   = (y < 2) ? (q2_w + (long)y*128*128) : (k2_w + (long)(y-2)*128*128);
    const float* bia = (y < 2) ? (q2_b + y*128)           : (k2_b + (y-2)*128);
    const float* Bbase = g_buf2 + ((long)b*384 + ((y < 2) ? 0 : 128)) * HW2 + n0;
    gemm_db_conv2(A, Bbase, 128, As, Bs, t, acc);
    gemm128_store2(g_buf3 + ((long)b*512 + y*128) * HW2 + n0, bia, t, acc, HW2);
}

// attention GEMM
__global__ void __launch_bounds__(256,2) attn_gemm2(
    const float* __restrict__ kc, const float* __restrict__ knew)
{
    int z = blockIdx.z; int b = z / NFtot, f = z % NFtot;
    const float* Qp = g_qtok + (long)b * Ntok * D2;
    const float* Kp = (f < 2) ? (kc   + ((long)(b*2 + f)) * Ntok * D2)
                              : (knew + ((long)(b*2 + 1)) * Ntok * D2);
    int m0 = blockIdx.y * 128, n0 = blockIdx.x * 128;
    int t = threadIdx.x;
    int tx = t & 15, ty = t >> 4;
    __shared__ float As[2][16][132];
    __shared__ float Bs[2][16][132];
    u64 acc[8][4] = {};
    gemm_db_tt2(Qp + (long)m0 * D2, Kp + (long)n0 * D2, D2, As, Bs, t, acc);
    float* Cp = g_attn + (long)z * Ntok * Ntok;
    #pragma unroll
    for (int i = 0; i < 8; i++) {
        int m = (i < 4) ? (ty*4 + i) : (64 + ty*4 + i - 4);
        float2 p0 = unpk(acc[i][0]), p1 = unpk(acc[i][1]);
        float2 p2 = unpk(acc[i][2]), p3 = unpk(acc[i][3]);
        float4 o0 = {p0.x, p0.y, p1.x, p1.y};
        float4 o1 = {p2.x, p2.y, p3.x, p3.y};
        *(float4*)&Cp[(long)(m0+m)*Ntok + n0 + tx*4]      = o0;
        *(float4*)&Cp[(long)(m0+m)*Ntok + n0 + 64 + tx*4] = o1;
    }
}

// proj 1x1 GEMM with fused window de-permute gather
__global__ void __launch_bounds__(256,2) proj_gemm2(
    const float* __restrict__ W, const float* __restrict__ bias,
    float* __restrict__ Out)
{
    int z  = blockIdx.z;
    int n0 = blockIdx.x * 128;
    int t = threadIdx.x;
    int tx = t & 15, ty = t >> 4;
    __shared__ float As[2][16][132];
    __shared__ float Bs[2][16][132];
    u64 acc[8][4] = {};
    int row = t >> 1;
    int p = n0 + row;
    int h = p / HWd, w = p % HWd;
    int token = (h % HGd) * HGd + (w % HGd);
    int vbase = ((h / HGd) * 4 + (w / HGd)) * 128;
    {
        int kq = (t & 1) * 8;
        const float* Ap = W + (long)row * 128 + kq;
        const float* Bp = g_otok + ((long)z * Ntok + token) * VDdim + vbase + kq;
        float4 a0 = *(const float4*)(Ap);
        float4 a1 = *(const float4*)(Ap + 4);
        float4 b0 = *(const float4*)(Bp);
        float4 b1 = *(const float4*)(Bp + 4);
        As[0][kq+0][row]=a0.x; As[0][kq+1][row]=a0.y; As[0][kq+2][row]=a0.z; As[0][kq+3][row]=a0.w;
        As[0][kq+4][row]=a1.x; As[0][kq+5][row]=a1.y; As[0][kq+6][row]=a1.z; As[0][kq+7][row]=a1.w;
        Bs[0][kq+0][row]=b0.x; Bs[0][kq+1][row]=b0.y; Bs[0][kq+2][row]=b0.z; Bs[0][kq+3][row]=b0.w;
        Bs[0][kq+4][row]=b1.x; Bs[0][kq+5][row]=b1.y; Bs[0][kq+6][row]=b1.z; Bs[0][kq+7][row]=b1.w;
        __syncthreads();
        int buf = 0;
        for (int k0 = 16; k0 <= 128; k0 += 16) {
            if (k0 < 128) {
                a0 = *(const float4*)(Ap + k0);
                a1 = *(const float4*)(Ap + k0 + 4);
                b0 = *(const float4*)(Bp + k0);
                b1 = *(const float4*)(Bp + k0 + 4);
            }
            #pragma unroll
            for (int kk = 0; kk < 16; kk++)
                fma_step(&As[buf][kk][0], &Bs[buf][kk][0], tx, ty, acc);
            if (k0 < 128) {
                int nb = buf ^ 1;
                As[nb][kq+0][row]=a0.x; As[nb][kq+1][row]=a0.y; As[nb][kq+2][row]=a0.z; As[nb][kq+3][row]=a0.w;
                As[nb][kq+4][row]=a1.x; As[nb][kq+5][row]=a1.y; As[nb][kq+6][row]=a1.z; As[nb][kq+7][row]=a1.w;
                Bs[nb][kq+0][row]=b0.x; Bs[nb][kq+1][row]=b0.y; Bs[nb][kq+2][row]=b0.z; Bs[nb][kq+3][row]=b0.w;
                Bs[nb][kq+4][row]=b1.x; Bs[nb][kq+5][row]=b1.y; Bs[nb][kq+6][row]=b1.z; Bs[nb][kq+7][row]=b1.w;
                __syncthreads();
                buf = nb;
            }
        }
    }
    #pragma unroll
    for (int i = 0; i < 8; i++) {
        int m = (i < 4) ? (ty*4 + i) : (64 + ty*4 + i - 4);
        float bv = bias[m];
        float2 p0 = unpk(acc[i][0]), p1 = unpk(acc[i][1]);
        float2 p2 = unpk(acc[i][2]), p3 = unpk(acc[i][3]);
        float4 o0 = {p0.x+bv, p0.y+bv, p1.x+bv, p1.y+bv};
        float4 o1 = {p2.x+bv, p2.y+bv, p3.x+bv, p3.y+bv};
        *(float4*)&Out[((long)z*128 + m)*HW2 + n0 + tx*4]      = o0;
        *(float4*)&Out[((long)z*128 + m)*HW2 + n0 + 64 + tx*4] = o1;
    }
}

// ---------------- depthwise 3x3 pad1 ------------------------------------------
__global__ void dw3x3(const float* __restrict__ qk_dw_w, const float* __restrict__ qk_dw_b,
                      const float* __restrict__ v_dw_w,  const float* __restrict__ v_dw_b)
{
    int idx = blockIdx.x * 256 + threadIdx.x;
    if (idx >= BATCH*384*HW2) return;
    int p  = idx % HW2;
    int ch = (idx / HW2) % 384;
    int b  = idx / (384*HW2);
    int h = p / HWd, w = p % HWd;
    const float* wgt; float bv;
    if (ch < 256) { wgt = qk_dw_w + ch*9;        bv = qk_dw_b[ch]; }
    else          { wgt = v_dw_w  + (ch-256)*9;  bv = v_dw_b[ch-256]; }
    const float* in = g_buf1 + ((long)(b*384 + ch)) * HW2;
    float s = bv;
    #pragma unroll
    for (int ky = 0; ky < 3; ky++) {
        int y = h + ky - 1;
        if ((unsigned)y >= (unsigned)HWd) continue;
        #pragma unroll
        for (int kx = 0; kx < 3; kx++) {
            int x = w + kx - 1;
            if ((unsigned)x >= (unsigned)HWd) continue;
            s += wgt[ky*3+kx] * in[y*HWd + x];
        }
    }
    g_buf2[idx] = s;
}

// ---------------- depthwise 4x4 stride4 pad1 ----------------------------------
__global__ void dw4x4(const float* __restrict__ q2_dw_w, const float* __restrict__ q2_dw_b,
                      const float* __restrict__ k2_dw_w, const float* __restrict__ k2_dw_b)
{
    int idx = blockIdx.x * 256 + threadIdx.x;
    if (idx >= BATCH*512*Ntok) return;
    int t  = idx % Ntok;
    int ch = (idx / Ntok) % 512;
    int b  = idx / (512*Ntok);
    int oy = t / HGd, ox = t % HGd;
    const float* wgt; float bv;
    if (ch < 256) { wgt = q2_dw_w + ch*16;       bv = q2_dw_b[ch]; }
    else          { wgt = k2_dw_w + (ch-256)*16; bv = k2_dw_b[ch-256]; }
    const float* in = g_buf3 + ((long)(b*512 + ch)) * HW2;
    float s = bv;
    #pragma unroll
    for (int ky = 0; ky < 4; ky++) {
        int y = oy*4 - 1 + ky;
        if ((unsigned)y >= (unsigned)HWd) continue;
        #pragma unroll
        for (int kx = 0; kx < 4; kx++) {
            int x = ox*4 - 1 + kx;
            if ((unsigned)x >= (unsigned)HWd) continue;
            s += wgt[ky*4+kx] * in[y*HWd + x];
        }
    }
    g_buf4[idx] = s;
}

// ---------------- l2 normalize + token-major q/k ------------------------------
__global__ void __launch_bounds__(256) norm_qk(float* __restrict__ kout,
                                               const float* __restrict__ temp)
{
    int token = blockIdx.x, b = blockIdx.y, d = threadIdx.x;
    float qv = g_buf4[((long)b*512 + d)       * Ntok + token];
    float kv = g_buf4[((long)b*512 + 256 + d) * Ntok + token];
    __shared__ float red[256];
    __shared__ float qinv_s, kinv_s;
    red[d] = qv*qv; __syncthreads();
    for (int s = 128; s > 0; s >>= 1) { if (d < s) red[d] += red[d+s]; __syncthreads(); }
    if (d == 0) qinv_s = (*temp) / fmaxf(sqrtf(red[0]), 1e-12f);
    __syncthreads();
    red[d] = kv*kv; __syncthreads();
    for (int s = 128; s > 0; s >>= 1) { if (d < s) red[d] += red[d+s]; __syncthreads(); }
    if (d == 0) kinv_s = 1.f / fmaxf(sqrtf(red[0]), 1e-12f);
    __syncthreads();
    g_qtok[((long)b*Ntok + token) * D2 + d] = qv * qinv_s;
    kout  [((long)(b*2 + 1)*Ntok + token) * D2 + d] = kv * kinv_s;
}

// ---------------- build v_new -------------------------------------------------
__global__ void build_vnew(float* __restrict__ vout)
{
    int idx = blockIdx.x * 256 + threadIdx.x;
    if (idx >= BATCH*Ntok*VDdim) return;
    int vd    = idx % VDdim;
    int token = (idx / VDdim) % Ntok;
    int b     = idx / (Ntok*VDdim);
    int c  = vd & 127;
    int p2 = (vd >> 7) & 3;
    int p1 = vd >> 9;
    int hi = token / HGd, wi = token % HGd;
    float val = g_buf2[((long)(b*384 + 256 + c)) * HW2 + (p1*HGd + hi) * HWd + (p2*HGd + wi)];
    vout[((long)(b*2 + 1)*Ntok + token) * VDdim + vd] = val;
}

// =============================================================================
// sparse_attn_av4: one block = 2x2 query tile, union-list AV with register
// reuse. Selection redone with warp-collective reductions (warp 0 merges the
// 1280 top-5 candidates via shfl; softmax max/sum via shfl) — ~8 syncthreads
// per query instead of ~48, no serial tid==0 loops.
// =============================================================================
__global__ void __launch_bounds__(256) sparse_attn_av4(
    const float* __restrict__ v_cached, const float* __restrict__ vout)
{
    int tile = blockIdx.x;               // 0..575
    int z    = blockIdx.y;               // b*3+f
    int b = z / NFtot, f = z % NFtot;
    int qy0 = (tile / 24) * 2, qx0 = (tile % 24) * 2;
    int tid = threadIdx.x;

    __shared__ float rowbuf[Ntok];
    __shared__ float cand[256*5];
    __shared__ float bcast;
    __shared__ int   sidx[4][LISTCAP];
    __shared__ float sval[4][LISTCAP];
    __shared__ int   scnt[4];
    __shared__ unsigned umask[72];
    __shared__ int   ubase[73];
    __shared__ int   nnz;
    __shared__ int   uidx[MAXU];
    __shared__ float Wt[4][MAXU];

    if (tid < 72) umask[tid] = 0;

    for (int q = 0; q < 4; q++) {
        int ny = qy0 + (q >> 1), nx = qx0 + (q & 1);
        int n = ny * HGd + nx;
        const float* arow = g_attn + ((long)z * Ntok + n) * Ntok;
        __syncthreads();
        for (int m = tid*4; m < Ntok; m += 1024)
            *(float4*)&rowbuf[m] = *(const float4*)&arow[m];
        if (tid == 0) nnz = 0;
        __syncthreads();

        // per-thread top-5
        float t5[5] = {-INFINITY,-INFINITY,-INFINITY,-INFINITY,-INFINITY};
        for (int m = tid; m < Ntok; m += 256) {
            float v = rowbuf[m];
            if (v > t5[4]) {
                t5[4] = v;
                #pragma unroll
                for (int i = 4; i > 0; i--)
                    if (t5[i] > t5[i-1]) { float tmp = t5[i-1]; t5[i-1] = t5[i]; t5[i] = tmp; }
            }
        }
        #pragma unroll
        for (int i = 0; i < 5; i++) cand[tid*5 + i] = t5[i];
        __syncthreads();

        // warp 0 merges 1280 candidates -> kth largest (strict-< exclusion)
        if (tid < 32) {
            float l5[5] = {-INFINITY,-INFINITY,-INFINITY,-INFINITY,-INFINITY};
            const float* cp = cand + tid*40;
            #pragma unroll
            for (int i = 0; i < 40; i++) {
                float v = cp[i];
                if (v > l5[4]) {
                    l5[4] = v;
                    #pragma unroll
                    for (int j = 4; j > 0; j--)
                        if (l5[j] > l5[j-1]) { float tmp = l5[j-1]; l5[j-1] = l5[j]; l5[j] = tmp; }
                }
            }
            float thr = INFINITY;
            #pragma unroll
            for (int r = 0; r < 5; r++) {
                float lm = -INFINITY;
                #pragma unroll
                for (int i = 0; i < 5; i++) {
                    float v = l5[i];
                    if (v < thr && v > lm) lm = v;
                }
                #pragma unroll
                for (int o = 16; o > 0; o >>= 1)
                    lm = fmaxf(lm, __shfl_xor_sync(0xffffffffu, lm, o));
                thr = lm;
            }
            if (tid == 0) bcast = thr;
        }
        __syncthreads();
        float kth = bcast;

        // collect nonzero entries; OR into union bitmap
        for (int m = tid; m < Ntok; m += 256) {
            float a = rowbuf[m];
            float coef = (a >= kth) ? 1.f : 0.f;
            int my = m / HGd, mx = m % HGd;
            if (abs(ny - my) + abs(nx - mx) <= 4) coef += 1.f;
            float v = a * coef;
            if (v != 0.f) {
                int pos = atomicAdd(&nnz, 1);
                if (pos < LISTCAP) { sidx[q][pos] = m; sval[q][pos] = v; }
                atomicOr(&umask[m >> 5], 1u << (m & 31));
            }
        }
        __syncthreads();
        int cnt = min(nnz, LISTCAP);

        // softmax: warp-0 max, block exp, warp-0 sum, block divide
        if (tid < 32) {
            float mx = -INFINITY;
            for (int e = tid; e < cnt; e += 32) mx = fmaxf(mx, sval[q][e]);
            #pragma unroll
            for (int o = 16; o > 0; o >>= 1)
                mx = fmaxf(mx, __shfl_xor_sync(0xffffffffu, mx, o));
            if (tid == 0) bcast = mx;
        }
        __syncthreads();
        float mxv = bcast;
        if (tid < cnt) sval[q][tid] = expf(sval[q][tid] - mxv);
        __syncthreads();
        if (tid < 32) {
            float s = 0.f;
            for (int e = tid; e < cnt; e += 32) s += sval[q][e];
            #pragma unroll
            for (int o = 16; o > 0; o >>= 1)
                s += __shfl_xor_sync(0xffffffffu, s, o);
            if (tid == 0) { bcast = s; scnt[q] = cnt; }
        }
        __syncthreads();
        if (tid < cnt) sval[q][tid] = sval[q][tid] / bcast;
    }
    __syncthreads();

    // union prefix ranks
    if (tid == 0) {
        int s = 0;
        for (int w = 0; w < 72; w++) { ubase[w] = s; s += __popc(umask[w]); }
        ubase[72] = s;
    }
    __syncthreads();
    int U = min(ubase[72], MAXU);

    // zero weight table, build union index list
    for (int i = tid; i < 4*MAXU; i += 256) ((float*)Wt)[i] = 0.f;
    __syncthreads();
    if (tid < 72) {
        unsigned bits = umask[tid];
        int pos = ubase[tid];
        while (bits) {
            int bit = __ffs(bits) - 1; bits &= bits - 1;
            if (pos < MAXU) uidx[pos] = tid*32 + bit;
            pos++;
        }
    }
    __syncthreads();
    // scatter per-query weights by union rank
    for (int i = tid; i < 4*LISTCAP; i += 256) {
        int q = i >> 7, e = i & (LISTCAP-1);
        if (e < scnt[q]) {
            int m = sidx[q][e];
            int w32 = m >> 5, bit = m & 31;
            int rank = ubase[w32] + __popc(umask[w32] & ((1u << bit) - 1u));
            if (rank < MAXU) Wt[q][rank] = sval[q][e];
        }
    }
    __syncthreads();

    // AV over union list: one load, 4 accumulator sets
    const float* vbase = (f < 2) ? (v_cached + ((long)(b*2 + f)) * Ntok * VDdim)
                                 : (vout     + ((long)(b*2 + 1)) * Ntok * VDdim);
    int d0 = tid * 8;
    float a0_[8] = {}, a1_[8] = {}, a2_[8] = {}, a3_[8] = {};
    for (int e = 0; e < U; e++) {
        int m = uidx[e];
        const float* vr = vbase + (long)m * VDdim + d0;
        float4 v0 = *(const float4*)vr;
        float4 v1 = *(const float4*)(vr + 4);
        float w0 = Wt[0][e], w1 = Wt[1][e], w2 = Wt[2][e], w3 = Wt[3][e];
        a0_[0]+=w0*v0.x; a0_[1]+=w0*v0.y; a0_[2]+=w0*v0.z; a0_[3]+=w0*v0.w;
        a0_[4]+=w0*v1.x; a0_[5]+=w0*v1.y; a0_[6]+=w0*v1.z; a0_[7]+=w0*v1.w;
        a1_[0]+=w1*v0.x; a1_[1]+=w1*v0.y; a1_[2]+=w1*v0.z; a1_[3]+=w1*v0.w;
        a1_[4]+=w1*v1.x; a1_[5]+=w1*v1.y; a1_[6]+=w1*v1.z; a1_[7]+=w1*v1.w;
        a2_[0]+=w2*v0.x; a2_[1]+=w2*v0.y; a2_[2]+=w2*v0.z; a2_[3]+=w2*v0.w;
        a2_[4]+=w2*v1.x; a2_[5]+=w2*v1.y; a2_[6]+=w2*v1.z; a2_[7]+=w2*v1.w;
        a3_[0]+=w3*v0.x; a3_[1]+=w3*v0.y; a3_[2]+=w3*v0.z; a3_[3]+=w3*v0.w;
        a3_[4]+=w3*v1.x; a3_[5]+=w3*v1.y; a3_[6]+=w3*v1.z; a3_[7]+=w3*v1.w;
    }
    #pragma unroll
    for (int q = 0; q < 4; q++) {
        const float* acc = (q == 0) ? a0_ : (q == 1) ? a1_ : (q == 2) ? a2_ : a3_;
        int ny = qy0 + (q >> 1), nx = qx0 + (q & 1);
        float* orow = g_otok + ((long)z * Ntok + ny*HGd + nx) * VDdim + d0;
        *(float4*)orow       = make_float4(acc[0], acc[1], acc[2], acc[3]);
        *(float4*)(orow + 4) = make_float4(acc[4], acc[5], acc[6], acc[7]);
    }
}

// ---------------------------------- launch -----------------------------------
extern "C" void kernel_launch(void* const* d_in, const int* in_sizes, int n_in,
                              void* d_out, int out_size)
{
    (void)in_sizes; (void)n_in; (void)out_size;
    const float* x         = (const float*)d_in[0];
    const float* k_cached  = (const float*)d_in[1];
    const float* v_cached  = (const float*)d_in[2];
    const float* temperature = (const float*)d_in[3];
    const float* qk_w  = (const float*)d_in[4],  *qk_b  = (const float*)d_in[5];
    const float* qk_dw_w = (const float*)d_in[6], *qk_dw_b = (const float*)d_in[7];
    const float* v_w   = (const float*)d_in[8],  *v_b   = (const float*)d_in[9];
    const float* v_dw_w = (const float*)d_in[10], *v_dw_b = (const float*)d_in[11];
    const float* k2_w  = (const float*)d_in[12], *k2_b  = (const float*)d_in[13];
    const float* k2_dw_w = (const float*)d_in[14], *k2_dw_b = (const float*)d_in[15];
    const float* q2_w  = (const float*)d_in[16], *q2_b  = (const float*)d_in[17];
    const float* q2_dw_w = (const float*)d_in[18], *q2_dw_b = (const float*)d_in[19];
    const float* proj_w = (const float*)d_in[20], *proj_b = (const float*)d_in[21];

    float* out = (float*)d_out;
    const long OUT_K = (long)BATCH * NFtot * 128 * HW2;
    const long OUT_V = OUT_K + (long)BATCH * 2 * Ntok * D2;
    float* kout = out + OUT_K;
    float* vout = out + OUT_V;

    dim3 blk(256);

    gemm_stageA<<<dim3(288,3,BATCH), blk>>>(x, qk_w, qk_b, v_w, v_b);
    dw3x3<<<(BATCH*384*HW2 + 255)/256, blk>>>(qk_dw_w, qk_dw_b, v_dw_w, v_dw_b);
    gemm_stageC<<<dim3(288,4,BATCH), blk>>>(q2_w, q2_b, k2_w, k2_b);
    dw4x4<<<(BATCH*512*Ntok + 255)/256, blk>>>(q2_dw_w, q2_dw_b, k2_dw_w, k2_dw_b);
    norm_qk<<<dim3(Ntok, BATCH), blk>>>(kout, temperature);
    build_vnew<<<(BATCH*Ntok*VDdim + 255)/256, blk>>>(vout);
    for (int b = 0; b < BATCH; b++) {
        cudaMemcpyAsync(kout + (long)(b*2)*Ntok*D2,
                        k_cached + (long)(b*2+1)*Ntok*D2,
                        (size_t)Ntok*D2*sizeof(float), cudaMemcpyDeviceToDevice, 0);
        cudaMemcpyAsync(vout + (long)(b*2)*Ntok*VDdim,
                        v_cached + (long)(b*2+1)*Ntok*VDdim,
                        (size_t)Ntok*VDdim*sizeof(float), cudaMemcpyDeviceToDevice, 0);
    }
    attn_gemm2<<<dim3(18,18,BATCH*NFtot), blk>>>(k_cached, kout);
    sparse_attn_av4<<<dim3(576, BATCH*NFtot), blk>>>(v_cached, vout);
    proj_gemm2<<<dim3(288,1,BATCH*NFtot), blk>>>(proj_w, proj_b, out);
}